// round 2
// baseline (speedup 1.0000x reference)
#include <cuda_runtime.h>
#include <math.h>

#define Bn 8
#define Cc 512
#define HW 4096
#define Mm 1024
#define Dd 64
#define Gg 128

// ---------------- scratch (device globals; no allocation allowed) ----------
__device__ float d_tpg[Bn * 256 * HW];   // rows 0..63 theta, 64..127 phi, 128..255 g  (32 MB)
__device__ float d_phiP[Bn * Dd * Mm];   // pooled phi [b][c][m]
__device__ float d_gP[Bn * Gg * Mm];     // pooled g   [b][g][m]
__device__ float d_yT[Bn * Gg * HW];     // attention output, [b][g][n] (16 MB)
__device__ float d_S[Gg * Gg];           // sum over b,n of y y^T
__device__ float d_mu[Gg];               // sum over b,n of y
__device__ float d_meanC[Cc];
__device__ float d_rstdC[Cc];

// ---------------- kernel 0: zero S -----------------------------------------
__global__ void zero_kernel() {
    int i = blockIdx.x * 256 + threadIdx.x;
    if (i < Gg * Gg) d_S[i] = 0.0f;
}

// ---------------- kernel 1: fused conv1x1 (theta|phi|g) --------------------
// C = W[256,512] @ x_b[512,4096], tiled 128x128, 256 thr, 8x8 micro
__global__ __launch_bounds__(256, 2) void gemm1_kernel(
    const float* __restrict__ x,
    const float* __restrict__ g_w, const float* __restrict__ g_b,
    const float* __restrict__ th_w, const float* __restrict__ th_b,
    const float* __restrict__ ph_w, const float* __restrict__ ph_b)
{
    __shared__ float As[16][128];
    __shared__ float Bs[16][128];
    __shared__ float bias_s[128];

    const int b = blockIdx.z;
    const int row0 = blockIdx.y * 128;
    const int n0 = blockIdx.x * 128;
    const int tid = threadIdx.x;
    const int tx = tid & 15, ty = tid >> 4;
    const float* xb = x + (size_t)b * Cc * HW;

    if (tid < 128) {
        int o = row0 + tid;
        float bv;
        if (o < 64) bv = th_b[o];
        else if (o < 128) bv = ph_b[o - 64];
        else bv = g_b[o - 128];
        bias_s[tid] = bv;
    }

    float acc[8][8];
#pragma unroll
    for (int i = 0; i < 8; i++)
#pragma unroll
        for (int j = 0; j < 8; j++) acc[i][j] = 0.0f;

    const int am = tid >> 1;
    const int akq = (tid & 1) * 8;
    const float* wrow;
    {
        int o = row0 + am;
        if (o < 64) wrow = th_w + (size_t)o * Cc;
        else if (o < 128) wrow = ph_w + (size_t)(o - 64) * Cc;
        else wrow = g_w + (size_t)(o - 128) * Cc;
    }
    const int bkk = tid >> 4;
    const int bnq = (tid & 15) * 8;

    for (int k0 = 0; k0 < Cc; k0 += 16) {
        float4 wa = *(const float4*)(wrow + k0 + akq);
        float4 wb = *(const float4*)(wrow + k0 + akq + 4);
        As[akq + 0][am] = wa.x; As[akq + 1][am] = wa.y;
        As[akq + 2][am] = wa.z; As[akq + 3][am] = wa.w;
        As[akq + 4][am] = wb.x; As[akq + 5][am] = wb.y;
        As[akq + 6][am] = wb.z; As[akq + 7][am] = wb.w;

        const float* src = xb + (size_t)(k0 + bkk) * HW + n0 + bnq;
        float4 v0 = *(const float4*)src;
        float4 v1 = *(const float4*)(src + 4);
        *(float4*)&Bs[bkk][bnq] = v0;
        *(float4*)&Bs[bkk][bnq + 4] = v1;
        __syncthreads();

#pragma unroll
        for (int kk = 0; kk < 16; kk++) {
            float4 a0 = *(float4*)&As[kk][ty * 8];
            float4 a1 = *(float4*)&As[kk][ty * 8 + 4];
            float4 b0 = *(float4*)&Bs[kk][tx * 8];
            float4 b1 = *(float4*)&Bs[kk][tx * 8 + 4];
            float ar[8] = {a0.x, a0.y, a0.z, a0.w, a1.x, a1.y, a1.z, a1.w};
            float br[8] = {b0.x, b0.y, b0.z, b0.w, b1.x, b1.y, b1.z, b1.w};
#pragma unroll
            for (int i = 0; i < 8; i++)
#pragma unroll
                for (int j = 0; j < 8; j++) acc[i][j] += ar[i] * br[j];
        }
        __syncthreads();
    }

    float* outp = d_tpg + ((size_t)b * 256 + row0) * HW + n0;
#pragma unroll
    for (int i = 0; i < 8; i++) {
        int r = ty * 8 + i;
        float bv = bias_s[r];
        float4 o0, o1;
        o0.x = acc[i][0] + bv; o0.y = acc[i][1] + bv;
        o0.z = acc[i][2] + bv; o0.w = acc[i][3] + bv;
        o1.x = acc[i][4] + bv; o1.y = acc[i][5] + bv;
        o1.z = acc[i][6] + bv; o1.w = acc[i][7] + bv;
        *(float4*)(outp + (size_t)r * HW + tx * 8) = o0;
        *(float4*)(outp + (size_t)r * HW + tx * 8 + 4) = o1;
    }
}

// ---------------- kernel 2: 2x2 maxpool of phi/g rows ----------------------
__global__ void pool_kernel() {
    int idx = blockIdx.x * 256 + threadIdx.x;
    if (idx >= Bn * 192 * Mm) return;
    int pm = idx & (Mm - 1);
    int c = (idx >> 10) % 192;
    int b = idx / (192 * Mm);
    int ph = pm >> 5, pw = pm & 31;
    const float* src = d_tpg + ((size_t)b * 256 + 64 + c) * HW + (size_t)(ph * 2) * 64 + pw * 2;
    float v = fmaxf(fmaxf(src[0], src[1]), fmaxf(src[64], src[65]));
    if (c < 64) d_phiP[((size_t)b * Dd + c) * Mm + pm] = v;
    else d_gP[((size_t)b * Gg + (c - 64)) * Mm + pm] = v;
}

// ---------------- kernel 3: fused attention (flash-style) ------------------
// per block: 64 query rows, loop M=1024 in tiles of 64
// smem: th[64][64] | phi[64][64] | P[64 m][65 r] | G[64 m][132 g]
#define ATT_SMEM_FLOATS (4096 + 4096 + 64 * 65 + 64 * 132)
__global__ __launch_bounds__(256, 2) void attn_kernel() {
    extern __shared__ float sm[];
    float* th_s = sm;
    float* phi_s = sm + 4096;
    float* P_s = sm + 8192;
    float* G_s = sm + 8192 + 64 * 65;

    const int b = blockIdx.y;
    const int n0 = blockIdx.x * 64;
    const int tid = threadIdx.x;
    const int tx = tid & 15, ty = tid >> 4;
    const int ty4 = ty * 4, tx4 = tx * 4, tx8 = tx * 8;

    const float* thg = d_tpg + (size_t)b * 256 * HW;
    for (int i = tid; i < 64 * 16; i += 256) {
        int c = i >> 4, rq = (i & 15) * 4;
        *(float4*)&th_s[c * 64 + rq] = *(const float4*)(thg + (size_t)c * HW + n0 + rq);
    }

    float rm[4], l[4], acc[4][8];
#pragma unroll
    for (int i = 0; i < 4; i++) { rm[i] = -1e30f; l[i] = 0.0f; }
#pragma unroll
    for (int i = 0; i < 4; i++)
#pragma unroll
        for (int j = 0; j < 8; j++) acc[i][j] = 0.0f;

    const float* phig = d_phiP + (size_t)b * Dd * Mm;
    const float* gg = d_gP + (size_t)b * Gg * Mm;

    for (int m0 = 0; m0 < Mm; m0 += 64) {
        for (int i = tid; i < 64 * 16; i += 256) {
            int c = i >> 4, mq = (i & 15) * 4;
            *(float4*)&phi_s[c * 64 + mq] = *(const float4*)(phig + (size_t)c * Mm + m0 + mq);
        }
        for (int i = tid; i < 128 * 16; i += 256) {
            int g = i >> 4, mq = (i & 15) * 4;
            float4 v = *(const float4*)(gg + (size_t)g * Mm + m0 + mq);
            G_s[(mq + 0) * 132 + g] = v.x;
            G_s[(mq + 1) * 132 + g] = v.y;
            G_s[(mq + 2) * 132 + g] = v.z;
            G_s[(mq + 3) * 132 + g] = v.w;
        }
        __syncthreads();

        // scores S[4][4]
        float s[4][4];
#pragma unroll
        for (int i = 0; i < 4; i++)
#pragma unroll
            for (int j = 0; j < 4; j++) s[i][j] = 0.0f;
#pragma unroll 8
        for (int c = 0; c < 64; c++) {
            float4 a = *(float4*)&th_s[c * 64 + ty4];
            float4 bb = *(float4*)&phi_s[c * 64 + tx4];
            float av[4] = {a.x, a.y, a.z, a.w};
            float bv[4] = {bb.x, bb.y, bb.z, bb.w};
#pragma unroll
            for (int i = 0; i < 4; i++)
#pragma unroll
                for (int j = 0; j < 4; j++) s[i][j] += av[i] * bv[j];
        }

        // online softmax over this tile; row groups are 16 consecutive lanes
        float scale[4];
#pragma unroll
        for (int i = 0; i < 4; i++) {
            float mx = fmaxf(fmaxf(s[i][0], s[i][1]), fmaxf(s[i][2], s[i][3]));
#pragma unroll
            for (int off = 8; off >= 1; off >>= 1)
                mx = fmaxf(mx, __shfl_xor_sync(0xffffffffu, mx, off));
            float nm = fmaxf(rm[i], mx);
            scale[i] = __expf(rm[i] - nm);
            rm[i] = nm;
            float ps = 0.0f;
#pragma unroll
            for (int j = 0; j < 4; j++) {
                s[i][j] = __expf(s[i][j] - nm);
                ps += s[i][j];
            }
#pragma unroll
            for (int off = 8; off >= 1; off >>= 1)
                ps += __shfl_xor_sync(0xffffffffu, ps, off);
            l[i] = l[i] * scale[i] + ps;
        }
        // store P transposed [m][r], rescale acc
#pragma unroll
        for (int j = 0; j < 4; j++)
#pragma unroll
            for (int i = 0; i < 4; i++)
                P_s[(tx4 + j) * 65 + ty4 + i] = s[i][j];
#pragma unroll
        for (int i = 0; i < 4; i++)
#pragma unroll
            for (int j = 0; j < 8; j++) acc[i][j] *= scale[i];
        __syncthreads();

        // y += P * G
#pragma unroll 4
        for (int m = 0; m < 64; m++) {
            float p0 = P_s[m * 65 + ty4 + 0];
            float p1 = P_s[m * 65 + ty4 + 1];
            float p2 = P_s[m * 65 + ty4 + 2];
            float p3 = P_s[m * 65 + ty4 + 3];
            float4 g0 = *(float4*)&G_s[m * 132 + tx8];
            float4 g1 = *(float4*)&G_s[m * 132 + tx8 + 4];
            float gv[8] = {g0.x, g0.y, g0.z, g0.w, g1.x, g1.y, g1.z, g1.w};
#pragma unroll
            for (int j = 0; j < 8; j++) {
                acc[0][j] += p0 * gv[j];
                acc[1][j] += p1 * gv[j];
                acc[2][j] += p2 * gv[j];
                acc[3][j] += p3 * gv[j];
            }
        }
        __syncthreads();
    }

    // finalize: y = acc / l, stage transposed [g][r] then coalesced store
    float invl[4];
#pragma unroll
    for (int i = 0; i < 4; i++) invl[i] = 1.0f / l[i];
    float* yst = sm;  // reuse th|phi region: 8192 floats, exactly 128*64
#pragma unroll
    for (int j = 0; j < 8; j++)
#pragma unroll
        for (int i = 0; i < 4; i++)
            yst[(tx8 + j) * 64 + ty4 + i] = acc[i][j] * invl[i];
    __syncthreads();

    float* yout = d_yT + (size_t)b * Gg * HW + n0;
    for (int i = tid; i < 128 * 16; i += 256) {
        int g = i >> 4, rq = (i & 15) * 4;
        *(float4*)(yout + (size_t)g * HW + rq) = *(float4*)&yst[g * 64 + rq];
    }
}

// ---------------- kernel 4: mu[g] = sum_{b,n} y -----------------------------
__global__ void mu_kernel() {
    int g = blockIdx.x;
    int tid = threadIdx.x;
    float s = 0.0f;
    const float* p = d_yT + (size_t)g * HW;
    for (int b = 0; b < Bn; b++) {
        for (int n = tid; n < HW; n += 256) s += p[n];
        p += (size_t)Gg * HW;
    }
    __shared__ float red[256];
    red[tid] = s;
    __syncthreads();
    for (int off = 128; off >= 1; off >>= 1) {
        if (tid < off) red[tid] += red[tid + off];
        __syncthreads();
    }
    if (tid == 0) d_mu[g] = red[0];
}

// ---------------- kernel 5: S = sum Y Y^T (syrk, atomic partials) ----------
__global__ __launch_bounds__(256, 2) void stats_kernel() {
    __shared__ float ys[32 * 132];  // [nn][g], padded
    const int b = blockIdx.x >> 4;
    const int nbase = (blockIdx.x & 15) * 256;
    const int tid = threadIdx.x;
    const int tx = tid & 15, ty = tid >> 4;

    float Sa[8][8];
#pragma unroll
    for (int i = 0; i < 8; i++)
#pragma unroll
        for (int j = 0; j < 8; j++) Sa[i][j] = 0.0f;

    const float* yb = d_yT + (size_t)b * Gg * HW + nbase;
    for (int nc = 0; nc < 256; nc += 32) {
        for (int i = tid; i < 1024; i += 256) {
            int g = i >> 3, nq = (i & 7) * 4;
            float4 v = *(const float4*)(yb + (size_t)g * HW + nc + nq);
            ys[(nq + 0) * 132 + g] = v.x;
            ys[(nq + 1) * 132 + g] = v.y;
            ys[(nq + 2) * 132 + g] = v.z;
            ys[(nq + 3) * 132 + g] = v.w;
        }
        __syncthreads();
#pragma unroll 4
        for (int nn = 0; nn < 32; nn++) {
            float4 u0 = *(float4*)&ys[nn * 132 + ty * 8];
            float4 u1 = *(float4*)&ys[nn * 132 + ty * 8 + 4];
            float4 v0 = *(float4*)&ys[nn * 132 + tx * 8];
            float4 v1 = *(float4*)&ys[nn * 132 + tx * 8 + 4];
            float ur[8] = {u0.x, u0.y, u0.z, u0.w, u1.x, u1.y, u1.z, u1.w};
            float vr[8] = {v0.x, v0.y, v0.z, v0.w, v1.x, v1.y, v1.z, v1.w};
#pragma unroll
            for (int i = 0; i < 8; i++)
#pragma unroll
                for (int j = 0; j < 8; j++) Sa[i][j] += ur[i] * vr[j];
        }
        __syncthreads();
    }
#pragma unroll
    for (int i = 0; i < 8; i++)
#pragma unroll
        for (int j = 0; j < 8; j++)
            atomicAdd(&d_S[(ty * 8 + i) * Gg + tx * 8 + j], Sa[i][j]);
}

// ---------------- kernel 6: per-channel BN mean/rstd (analytic) ------------
__global__ void meanvar_kernel(const float* __restrict__ wz_w,
                               const float* __restrict__ wz_b) {
    const int c = blockIdx.x;
    const int g = threadIdx.x;
    __shared__ float wsh[Gg];
    __shared__ double red[Gg];
    wsh[g] = wz_w[(size_t)c * Gg + g];
    __syncthreads();
    double t = 0.0;
    for (int gp = 0; gp < Gg; gp++)
        t += (double)d_S[g * Gg + gp] * (double)wsh[gp];
    red[g] = t * (double)wsh[g];
    __syncthreads();
    for (int off = 64; off >= 1; off >>= 1) {
        if (g < off) red[g] += red[g + off];
        __syncthreads();
    }
    double wtsw = red[0];
    __syncthreads();
    red[g] = (double)wsh[g] * (double)d_mu[g];
    __syncthreads();
    for (int off = 64; off >= 1; off >>= 1) {
        if (g < off) red[g] += red[g + off];
        __syncthreads();
    }
    if (g == 0) {
        double wm = red[0];
        double inv = 1.0 / (double)(Bn * HW);
        double bz = (double)wz_b[c];
        double mean = wm * inv + bz;
        double e2 = wtsw * inv + 2.0 * bz * wm * inv + bz * bz;
        double var = e2 - mean * mean;
        d_meanC[c] = (float)mean;
        d_rstdC[c] = (float)rsqrt(var + 1e-5);
    }
}

// ---------------- kernel 7: wz GEMM + BN + residual ------------------------
__global__ __launch_bounds__(256, 2) void gemm2_kernel(
    const float* __restrict__ x,
    const float* __restrict__ wz_w, const float* __restrict__ wz_b,
    const float* __restrict__ gamma, const float* __restrict__ beta,
    float* __restrict__ out)
{
    __shared__ float As[16][128];
    __shared__ float Bs[16][128];
    const int b = blockIdx.z;
    const int c0 = blockIdx.y * 128;
    const int n0 = blockIdx.x * 128;
    const int tid = threadIdx.x;
    const int tx = tid & 15, ty = tid >> 4;

    float acc[8][8];
#pragma unroll
    for (int i = 0; i < 8; i++)
#pragma unroll
        for (int j = 0; j < 8; j++) acc[i][j] = 0.0f;

    const int am = tid >> 1;
    const int akq = (tid & 1) * 8;
    const float* wrow = wz_w + (size_t)(c0 + am) * Gg;
    const int bkk = tid >> 4;
    const int bnq = (tid & 15) * 8;
    const float* yb = d_yT + (size_t)b * Gg * HW;

    for (int k0 = 0; k0 < Gg; k0 += 16) {
        float4 wa = *(const float4*)(wrow + k0 + akq);
        float4 wb = *(const float4*)(wrow + k0 + akq + 4);
        As[akq + 0][am] = wa.x; As[akq + 1][am] = wa.y;
        As[akq + 2][am] = wa.z; As[akq + 3][am] = wa.w;
        As[akq + 4][am] = wb.x; As[akq + 5][am] = wb.y;
        As[akq + 6][am] = wb.z; As[akq + 7][am] = wb.w;

        const float* src = yb + (size_t)(k0 + bkk) * HW + n0 + bnq;
        float4 v0 = *(const float4*)src;
        float4 v1 = *(const float4*)(src + 4);
        *(float4*)&Bs[bkk][bnq] = v0;
        *(float4*)&Bs[bkk][bnq + 4] = v1;
        __syncthreads();

#pragma unroll
        for (int kk = 0; kk < 16; kk++) {
            float4 a0 = *(float4*)&As[kk][ty * 8];
            float4 a1 = *(float4*)&As[kk][ty * 8 + 4];
            float4 b0 = *(float4*)&Bs[kk][tx * 8];
            float4 b1 = *(float4*)&Bs[kk][tx * 8 + 4];
            float ar[8] = {a0.x, a0.y, a0.z, a0.w, a1.x, a1.y, a1.z, a1.w};
            float br[8] = {b0.x, b0.y, b0.z, b0.w, b1.x, b1.y, b1.z, b1.w};
#pragma unroll
            for (int i = 0; i < 8; i++)
#pragma unroll
                for (int j = 0; j < 8; j++) acc[i][j] += ar[i] * br[j];
        }
        __syncthreads();
    }

#pragma unroll
    for (int i = 0; i < 8; i++) {
        int c = c0 + ty * 8 + i;
        float mn = d_meanC[c], rs = d_rstdC[c];
        float ga = gamma[c], be = beta[c], bz = wz_b[c];
        float a = rs * ga;
        const float* xr = x + ((size_t)b * Cc + c) * HW + n0 + tx * 8;
        float* orow = out + ((size_t)b * Cc + c) * HW + n0 + tx * 8;
        float4 x0 = *(const float4*)xr;
        float4 x1 = *(const float4*)(xr + 4);
        float4 o0, o1;
        o0.x = (acc[i][0] + bz - mn) * a + be + x0.x;
        o0.y = (acc[i][1] + bz - mn) * a + be + x0.y;
        o0.z = (acc[i][2] + bz - mn) * a + be + x0.z;
        o0.w = (acc[i][3] + bz - mn) * a + be + x0.w;
        o1.x = (acc[i][4] + bz - mn) * a + be + x1.x;
        o1.y = (acc[i][5] + bz - mn) * a + be + x1.y;
        o1.z = (acc[i][6] + bz - mn) * a + be + x1.z;
        o1.w = (acc[i][7] + bz - mn) * a + be + x1.w;
        *(float4*)orow = o0;
        *(float4*)(orow + 4) = o1;
    }
}

// ---------------- launch ----------------------------------------------------
extern "C" void kernel_launch(void* const* d_in, const int* in_sizes, int n_in,
                              void* d_out, int out_size) {
    const float* x = (const float*)d_in[0];
    const float* g_w = (const float*)d_in[1];
    const float* g_b = (const float*)d_in[2];
    const float* th_w = (const float*)d_in[3];
    const float* th_b = (const float*)d_in[4];
    const float* ph_w = (const float*)d_in[5];
    const float* ph_b = (const float*)d_in[6];
    const float* wz_w = (const float*)d_in[7];
    const float* wz_b = (const float*)d_in[8];
    const float* gamma = (const float*)d_in[9];
    const float* beta = (const float*)d_in[10];
    float* out = (float*)d_out;

    const int att_smem = ATT_SMEM_FLOATS * 4;
    // Idempotent; legal during graph capture (not a stream op).
    (void)cudaFuncSetAttribute(attn_kernel,
                               cudaFuncAttributeMaxDynamicSharedMemorySize, att_smem);

    zero_kernel<<<64, 256>>>();
    gemm1_kernel<<<dim3(HW / 128, 2, Bn), 256>>>(x, g_w, g_b, th_w, th_b, ph_w, ph_b);
    pool_kernel<<<(Bn * 192 * Mm + 255) / 256, 256>>>();
    attn_kernel<<<dim3(HW / 64, Bn), 256, att_smem>>>();
    mu_kernel<<<Gg, 256>>>();
    stats_kernel<<<128, 256>>>();
    meanvar_kernel<<<Cc, Gg>>>(wz_w, wz_b);
    gemm2_kernel<<<dim3(HW / 128, Cc / 128, Bn), 256>>>(x, wz_w, wz_b, gamma, beta, out);
}

// round 3
// speedup vs baseline: 1.1384x; 1.1384x over previous
#include <cuda_runtime.h>
#include <math.h>

#define Bn 8
#define Cc 512
#define HW 4096
#define Mm 1024
#define Dd 64
#define Gg 128

// ---------------- scratch (device globals; no allocation allowed) ----------
__device__ float d_tpg[Bn * 256 * HW];   // rows 0..63 theta, 64..127 phi, 128..255 g  (32 MB)
__device__ float d_phiP[Bn * Dd * Mm];   // pooled phi [b][c][m]
__device__ float d_gPT[Bn * Mm * Gg];    // pooled g, TRANSPOSED: [b][m][g]
__device__ float d_yT[Bn * Gg * HW];     // attention output, [b][g][n] (16 MB)
__device__ float d_S[Gg * Gg];           // sum over b,n of y y^T
__device__ float d_mu[Gg];               // sum over b,n of y
__device__ float d_meanC[Cc];
__device__ float d_rstdC[Cc];

// ---------------- fast exp on the FMA pipe (no MUFU) -----------------------
__device__ __forceinline__ float fast_exp(float x) {
    x = fmaxf(x, -87.0f);
    float t = fmaf(x, 1.4426950408889634f, 12582912.0f);   // round-to-nearest int
    float n = t - 12582912.0f;
    int e = __float_as_int(t) - 0x4B400000;                // integer n
    float r = fmaf(n, -6.93145752e-1f, x);                 // Cody-Waite hi
    r = fmaf(n, -1.42860677e-6f, r);                       // Cody-Waite lo
    float p = 1.3888889e-3f;                               // e^r Taylor deg-6
    p = fmaf(p, r, 8.3333333e-3f);
    p = fmaf(p, r, 4.1666668e-2f);
    p = fmaf(p, r, 1.6666667e-1f);
    p = fmaf(p, r, 5.0e-1f);
    p = fmaf(p, r, 1.0f);
    p = fmaf(p, r, 1.0f);
    return __int_as_float(__float_as_int(p) + (e << 23));  // * 2^n
}

// ---------------- kernel 0: zero S, mu -------------------------------------
__global__ void zero_kernel() {
    int i = blockIdx.x * 256 + threadIdx.x;
    if (i < Gg * Gg) d_S[i] = 0.0f;
    if (i < Gg) d_mu[i] = 0.0f;
}

// ---------------- kernel 1: fused conv1x1 (theta|phi|g) --------------------
__global__ __launch_bounds__(256, 2) void gemm1_kernel(
    const float* __restrict__ x,
    const float* __restrict__ g_w, const float* __restrict__ g_b,
    const float* __restrict__ th_w, const float* __restrict__ th_b,
    const float* __restrict__ ph_w, const float* __restrict__ ph_b)
{
    __shared__ float As[16][128];
    __shared__ float Bs[16][128];
    __shared__ float bias_s[128];

    const int b = blockIdx.z;
    const int row0 = blockIdx.y * 128;
    const int n0 = blockIdx.x * 128;
    const int tid = threadIdx.x;
    const int tx = tid & 15, ty = tid >> 4;
    const float* xb = x + (size_t)b * Cc * HW;

    if (tid < 128) {
        int o = row0 + tid;
        float bv;
        if (o < 64) bv = th_b[o];
        else if (o < 128) bv = ph_b[o - 64];
        else bv = g_b[o - 128];
        bias_s[tid] = bv;
    }

    float acc[8][8];
#pragma unroll
    for (int i = 0; i < 8; i++)
#pragma unroll
        for (int j = 0; j < 8; j++) acc[i][j] = 0.0f;

    const int am = tid >> 1;
    const int akq = (tid & 1) * 8;
    const float* wrow;
    {
        int o = row0 + am;
        if (o < 64) wrow = th_w + (size_t)o * Cc;
        else if (o < 128) wrow = ph_w + (size_t)(o - 64) * Cc;
        else wrow = g_w + (size_t)(o - 128) * Cc;
    }
    const int bkk = tid >> 4;
    const int bnq = (tid & 15) * 8;

    for (int k0 = 0; k0 < Cc; k0 += 16) {
        float4 wa = *(const float4*)(wrow + k0 + akq);
        float4 wb = *(const float4*)(wrow + k0 + akq + 4);
        As[akq + 0][am] = wa.x; As[akq + 1][am] = wa.y;
        As[akq + 2][am] = wa.z; As[akq + 3][am] = wa.w;
        As[akq + 4][am] = wb.x; As[akq + 5][am] = wb.y;
        As[akq + 6][am] = wb.z; As[akq + 7][am] = wb.w;

        const float* src = xb + (size_t)(k0 + bkk) * HW + n0 + bnq;
        float4 v0 = *(const float4*)src;
        float4 v1 = *(const float4*)(src + 4);
        *(float4*)&Bs[bkk][bnq] = v0;
        *(float4*)&Bs[bkk][bnq + 4] = v1;
        __syncthreads();

#pragma unroll
        for (int kk = 0; kk < 16; kk++) {
            float4 a0 = *(float4*)&As[kk][ty * 8];
            float4 a1 = *(float4*)&As[kk][ty * 8 + 4];
            float4 b0 = *(float4*)&Bs[kk][tx * 8];
            float4 b1 = *(float4*)&Bs[kk][tx * 8 + 4];
            float ar[8] = {a0.x, a0.y, a0.z, a0.w, a1.x, a1.y, a1.z, a1.w};
            float br[8] = {b0.x, b0.y, b0.z, b0.w, b1.x, b1.y, b1.z, b1.w};
#pragma unroll
            for (int i = 0; i < 8; i++)
#pragma unroll
                for (int j = 0; j < 8; j++) acc[i][j] += ar[i] * br[j];
        }
        __syncthreads();
    }

    float* outp = d_tpg + ((size_t)b * 256 + row0) * HW + n0;
#pragma unroll
    for (int i = 0; i < 8; i++) {
        int r = ty * 8 + i;
        float bv = bias_s[r];
        float4 o0, o1;
        o0.x = acc[i][0] + bv; o0.y = acc[i][1] + bv;
        o0.z = acc[i][2] + bv; o0.w = acc[i][3] + bv;
        o1.x = acc[i][4] + bv; o1.y = acc[i][5] + bv;
        o1.z = acc[i][6] + bv; o1.w = acc[i][7] + bv;
        *(float4*)(outp + (size_t)r * HW + tx * 8) = o0;
        *(float4*)(outp + (size_t)r * HW + tx * 8 + 4) = o1;
    }
}

// ---------------- kernel 2: 2x2 maxpool of phi/g rows ----------------------
// phi -> d_phiP [c][m];   g -> d_gPT [m][g]  (transposed for attention)
__global__ void pool_kernel() {
    int idx = blockIdx.x * 256 + threadIdx.x;
    if (idx >= Bn * 192 * Mm) return;
    int pm = idx & (Mm - 1);
    int c = (idx >> 10) % 192;
    int b = idx / (192 * Mm);
    int ph = pm >> 5, pw = pm & 31;
    const float* src = d_tpg + ((size_t)b * 256 + 64 + c) * HW + (size_t)(ph * 2) * 64 + pw * 2;
    float v = fmaxf(fmaxf(src[0], src[1]), fmaxf(src[64], src[65]));
    if (c < 64) d_phiP[((size_t)b * Dd + c) * Mm + pm] = v;
    else d_gPT[((size_t)b * Mm + pm) * Gg + (c - 64)] = v;
}

// ---------------- kernel 3: fused attention (flash-style) ------------------
// per block: 128 query rows (NT), loop M=1024 in tiles of 64 (MT)
// Score phase: n on ty (8/thr), m on tx (4/thr). PV phase: n on tx (8/thr), g on ty (8/thr).
// smem floats: th[64*128] | phi[64*64] | P[64*132] | G[64*132] | scale[128] | l[128]
#define ATT_SMEM_FLOATS (8192 + 4096 + 8448 + 8448 + 256)
__global__ __launch_bounds__(256, 1) void attn_kernel() {
    extern __shared__ float sm[];
    float* th_s = sm;                    // [c][n] stride 128
    float* phi_s = sm + 8192;            // [c][m] stride 64
    float* P_s = sm + 12288;             // [m][n] stride 132
    float* G_s = sm + 20736;             // [m][g] stride 132
    float* scale_s = sm + 29184;         // [128]
    float* l_s = sm + 29312;             // [128]

    const int b = blockIdx.y;
    const int n0 = blockIdx.x * 128;
    const int tid = threadIdx.x;
    const int tx = tid & 15, ty = tid >> 4;
    const int ty8 = ty * 8, tx4 = tx * 4, tx8 = tx * 8;

    // stage theta [c][n] once
    const float* thg = d_tpg + (size_t)b * 256 * HW + n0;
    for (int f = tid; f < 64 * 32; f += 256) {
        int c = f >> 5, nq = (f & 31) * 4;
        *(float4*)&th_s[c * 128 + nq] = *(const float4*)(thg + (size_t)c * HW + nq);
    }

    float rm[8], l[8], acc[8][8];
#pragma unroll
    for (int i = 0; i < 8; i++) { rm[i] = -1e30f; l[i] = 0.0f; }
#pragma unroll
    for (int i = 0; i < 8; i++)
#pragma unroll
        for (int j = 0; j < 8; j++) acc[i][j] = 0.0f;

    const float* phig = d_phiP + (size_t)b * Dd * Mm;
    const float* gTg = d_gPT + (size_t)b * Mm * Gg;

    for (int m0 = 0; m0 < Mm; m0 += 64) {
        __syncthreads();   // prev PV readers done before restaging
        // stage phi [c][m]
        for (int f = tid; f < 64 * 16; f += 256) {
            int c = f >> 4, mq = (f & 15) * 4;
            *(float4*)&phi_s[c * 64 + mq] = *(const float4*)(phig + (size_t)c * Mm + m0 + mq);
        }
        // stage G [m][g] (already transposed in gmem -> conflict-free copy)
        for (int f = tid; f < 64 * 32; f += 256) {
            int m = f >> 5, gq = (f & 31) * 4;
            *(float4*)&G_s[m * 132 + gq] = *(const float4*)(gTg + (size_t)(m0 + m) * Gg + gq);
        }
        __syncthreads();

        // scores s[8 n][4 m]
        float s[8][4];
#pragma unroll
        for (int i = 0; i < 8; i++)
#pragma unroll
            for (int j = 0; j < 4; j++) s[i][j] = 0.0f;
#pragma unroll 8
        for (int c = 0; c < 64; c++) {
            float4 a0 = *(float4*)&th_s[c * 128 + ty8];
            float4 a1 = *(float4*)&th_s[c * 128 + ty8 + 4];
            float4 bb = *(float4*)&phi_s[c * 64 + tx4];
            float av[8] = {a0.x, a0.y, a0.z, a0.w, a1.x, a1.y, a1.z, a1.w};
            float bv[4] = {bb.x, bb.y, bb.z, bb.w};
#pragma unroll
            for (int i = 0; i < 8; i++)
#pragma unroll
                for (int j = 0; j < 4; j++) s[i][j] += av[i] * bv[j];
        }

        // online softmax; rows reduce across the 16-lane tx group
        float sc[8];
#pragma unroll
        for (int i = 0; i < 8; i++) {
            float mx = fmaxf(fmaxf(s[i][0], s[i][1]), fmaxf(s[i][2], s[i][3]));
#pragma unroll
            for (int off = 8; off >= 1; off >>= 1)
                mx = fmaxf(mx, __shfl_xor_sync(0xffffffffu, mx, off));
            float nm = fmaxf(rm[i], mx);
            sc[i] = fast_exp(rm[i] - nm);
            rm[i] = nm;
            float ps = 0.0f;
#pragma unroll
            for (int j = 0; j < 4; j++) {
                s[i][j] = fast_exp(s[i][j] - nm);
                ps += s[i][j];
            }
#pragma unroll
            for (int off = 8; off >= 1; off >>= 1)
                ps += __shfl_xor_sync(0xffffffffu, ps, off);
            l[i] = l[i] * sc[i] + ps;
        }
        if (tx == 0) {
#pragma unroll
            for (int i = 0; i < 8; i++) scale_s[ty8 + i] = sc[i];
        }
        // store P [m][n] as float4 over n
#pragma unroll
        for (int j = 0; j < 4; j++) {
            float4 lo, hi;
            lo.x = s[0][j]; lo.y = s[1][j]; lo.z = s[2][j]; lo.w = s[3][j];
            hi.x = s[4][j]; hi.y = s[5][j]; hi.z = s[6][j]; hi.w = s[7][j];
            *(float4*)&P_s[(tx4 + j) * 132 + ty8] = lo;
            *(float4*)&P_s[(tx4 + j) * 132 + ty8 + 4] = hi;
        }
        __syncthreads();

        // rescale acc (PV rows n = tx8+r)
        {
            float4 s0 = *(float4*)&scale_s[tx8];
            float4 s1 = *(float4*)&scale_s[tx8 + 4];
            float sr[8] = {s0.x, s0.y, s0.z, s0.w, s1.x, s1.y, s1.z, s1.w};
#pragma unroll
            for (int r = 0; r < 8; r++)
#pragma unroll
                for (int u = 0; u < 8; u++) acc[r][u] *= sr[r];
        }
        // y += P * G  (vectorized P and broadcast G)
#pragma unroll 4
        for (int m = 0; m < 64; m++) {
            float4 p0 = *(float4*)&P_s[m * 132 + tx8];
            float4 p1 = *(float4*)&P_s[m * 132 + tx8 + 4];
            float4 g0 = *(float4*)&G_s[m * 132 + ty8];
            float4 g1 = *(float4*)&G_s[m * 132 + ty8 + 4];
            float pr[8] = {p0.x, p0.y, p0.z, p0.w, p1.x, p1.y, p1.z, p1.w};
            float gu[8] = {g0.x, g0.y, g0.z, g0.w, g1.x, g1.y, g1.z, g1.w};
#pragma unroll
            for (int r = 0; r < 8; r++)
#pragma unroll
                for (int u = 0; u < 8; u++) acc[r][u] += pr[r] * gu[u];
        }
    }

    __syncthreads();
    if (tx == 0) {
#pragma unroll
        for (int i = 0; i < 8; i++) l_s[ty8 + i] = l[i];
    }
    __syncthreads();

    float inv[8];
    {
        float4 l0 = *(float4*)&l_s[tx8];
        float4 l1 = *(float4*)&l_s[tx8 + 4];
        inv[0] = 1.0f / l0.x; inv[1] = 1.0f / l0.y;
        inv[2] = 1.0f / l0.z; inv[3] = 1.0f / l0.w;
        inv[4] = 1.0f / l1.x; inv[5] = 1.0f / l1.y;
        inv[6] = 1.0f / l1.z; inv[7] = 1.0f / l1.w;
    }
    __syncthreads();   // everyone has read l_s; smem free for staging

    // stage y as [g][n] stride 132 (conflict-free float4 stores over n)
    float* yst = sm;   // 128*132 = 16896 floats, fits below G_s region
#pragma unroll
    for (int u = 0; u < 8; u++) {
        float4 lo, hi;
        lo.x = acc[0][u] * inv[0]; lo.y = acc[1][u] * inv[1];
        lo.z = acc[2][u] * inv[2]; lo.w = acc[3][u] * inv[3];
        hi.x = acc[4][u] * inv[4]; hi.y = acc[5][u] * inv[5];
        hi.z = acc[6][u] * inv[6]; hi.w = acc[7][u] * inv[7];
        *(float4*)&yst[(ty8 + u) * 132 + tx8] = lo;
        *(float4*)&yst[(ty8 + u) * 132 + tx8 + 4] = hi;
    }
    __syncthreads();

    float* yout = d_yT + (size_t)b * Gg * HW + n0;
    for (int f = tid; f < 128 * 32; f += 256) {
        int g = f >> 5, nq = (f & 31) * 4;
        *(float4*)(yout + (size_t)g * HW + nq) = *(float4*)&yst[g * 132 + nq];
    }
}

// ---------------- kernel 4: mu[g] = sum_{b,n} y (atomic partials) ----------
__global__ void mu_kernel() {
    int g = blockIdx.x;
    int b = blockIdx.y;
    int tid = threadIdx.x;
    float s = 0.0f;
    const float* p = d_yT + ((size_t)b * Gg + g) * HW;
    for (int n = tid; n < HW; n += 256) s += p[n];
    __shared__ float red[256];
    red[tid] = s;
    __syncthreads();
    for (int off = 128; off >= 1; off >>= 1) {
        if (tid < off) red[tid] += red[tid + off];
        __syncthreads();
    }
    if (tid == 0) atomicAdd(&d_mu[g], red[0]);
}

// ---------------- kernel 5: S = sum Y Y^T (syrk, atomic partials) ----------
__global__ __launch_bounds__(256, 2) void stats_kernel() {
    __shared__ float ys[32 * 132];  // [nn][g], padded
    const int b = blockIdx.x >> 4;
    const int nbase = (blockIdx.x & 15) * 256;
    const int tid = threadIdx.x;
    const int tx = tid & 15, ty = tid >> 4;

    float Sa[8][8];
#pragma unroll
    for (int i = 0; i < 8; i++)
#pragma unroll
        for (int j = 0; j < 8; j++) Sa[i][j] = 0.0f;

    const float* yb = d_yT + (size_t)b * Gg * HW + nbase;
    for (int nc = 0; nc < 256; nc += 32) {
        for (int i = tid; i < 1024; i += 256) {
            int g = i >> 3, nq = (i & 7) * 4;
            float4 v = *(const float4*)(yb + (size_t)g * HW + nc + nq);
            ys[(nq + 0) * 132 + g] = v.x;
            ys[(nq + 1) * 132 + g] = v.y;
            ys[(nq + 2) * 132 + g] = v.z;
            ys[(nq + 3) * 132 + g] = v.w;
        }
        __syncthreads();
#pragma unroll 4
        for (int nn = 0; nn < 32; nn++) {
            float4 u0 = *(float4*)&ys[nn * 132 + ty * 8];
            float4 u1 = *(float4*)&ys[nn * 132 + ty * 8 + 4];
            float4 v0 = *(float4*)&ys[nn * 132 + tx * 8];
            float4 v1 = *(float4*)&ys[nn * 132 + tx * 8 + 4];
            float ur[8] = {u0.x, u0.y, u0.z, u0.w, u1.x, u1.y, u1.z, u1.w};
            float vr[8] = {v0.x, v0.y, v0.z, v0.w, v1.x, v1.y, v1.z, v1.w};
#pragma unroll
            for (int i = 0; i < 8; i++)
#pragma unroll
                for (int j = 0; j < 8; j++) Sa[i][j] += ur[i] * vr[j];
        }
        __syncthreads();
    }
#pragma unroll
    for (int i = 0; i < 8; i++)
#pragma unroll
        for (int j = 0; j < 8; j++)
            atomicAdd(&d_S[(ty * 8 + i) * Gg + tx * 8 + j], Sa[i][j]);
}

// ---------------- kernel 6: per-channel BN mean/rstd (analytic) ------------
__global__ void meanvar_kernel(const float* __restrict__ wz_w,
                               const float* __restrict__ wz_b) {
    const int c = blockIdx.x;
    const int g = threadIdx.x;
    __shared__ float wsh[Gg];
    __shared__ double red[Gg];
    wsh[g] = wz_w[(size_t)c * Gg + g];
    __syncthreads();
    double t = 0.0;
    for (int gp = 0; gp < Gg; gp++)
        t += (double)d_S[g * Gg + gp] * (double)wsh[gp];
    red[g] = t * (double)wsh[g];
    __syncthreads();
    for (int off = 64; off >= 1; off >>= 1) {
        if (g < off) red[g] += red[g + off];
        __syncthreads();
    }
    double wtsw = red[0];
    __syncthreads();
    red[g] = (double)wsh[g] * (double)d_mu[g];
    __syncthreads();
    for (int off = 64; off >= 1; off >>= 1) {
        if (g < off) red[g] += red[g + off];
        __syncthreads();
    }
    if (g == 0) {
        double wm = red[0];
        double inv = 1.0 / (double)(Bn * HW);
        double bz = (double)wz_b[c];
        double mean = wm * inv + bz;
        double e2 = wtsw * inv + 2.0 * bz * wm * inv + bz * bz;
        double var = e2 - mean * mean;
        d_meanC[c] = (float)mean;
        d_rstdC[c] = (float)rsqrt(var + 1e-5);
    }
}

// ---------------- kernel 7: wz GEMM + BN + residual ------------------------
__global__ __launch_bounds__(256, 2) void gemm2_kernel(
    const float* __restrict__ x,
    const float* __restrict__ wz_w, const float* __restrict__ wz_b,
    const float* __restrict__ gamma, const float* __restrict__ beta,
    float* __restrict__ out)
{
    __shared__ float As[16][128];
    __shared__ float Bs[16][128];
    const int b = blockIdx.z;
    const int c0 = blockIdx.y * 128;
    const int n0 = blockIdx.x * 128;
    const int tid = threadIdx.x;
    const int tx = tid & 15, ty = tid >> 4;

    float acc[8][8];
#pragma unroll
    for (int i = 0; i < 8; i++)
#pragma unroll
        for (int j = 0; j < 8; j++) acc[i][j] = 0.0f;

    const int am = tid >> 1;
    const int akq = (tid & 1) * 8;
    const float* wrow = wz_w + (size_t)(c0 + am) * Gg;
    const int bkk = tid >> 4;
    const int bnq = (tid & 15) * 8;
    const float* yb = d_yT + (size_t)b * Gg * HW;

    for (int k0 = 0; k0 < Gg; k0 += 16) {
        float4 wa = *(const float4*)(wrow + k0 + akq);
        float4 wb = *(const float4*)(wrow + k0 + akq + 4);
        As[akq + 0][am] = wa.x; As[akq + 1][am] = wa.y;
        As[akq + 2][am] = wa.z; As[akq + 3][am] = wa.w;
        As[akq + 4][am] = wb.x; As[akq + 5][am] = wb.y;
        As[akq + 6][am] = wb.z; As[akq + 7][am] = wb.w;

        const float* src = yb + (size_t)(k0 + bkk) * HW + n0 + bnq;
        float4 v0 = *(const float4*)src;
        float4 v1 = *(const float4*)(src + 4);
        *(float4*)&Bs[bkk][bnq] = v0;
        *(float4*)&Bs[bkk][bnq + 4] = v1;
        __syncthreads();

#pragma unroll
        for (int kk = 0; kk < 16; kk++) {
            float4 a0 = *(float4*)&As[kk][ty * 8];
            float4 a1 = *(float4*)&As[kk][ty * 8 + 4];
            float4 b0 = *(float4*)&Bs[kk][tx * 8];
            float4 b1 = *(float4*)&Bs[kk][tx * 8 + 4];
            float ar[8] = {a0.x, a0.y, a0.z, a0.w, a1.x, a1.y, a1.z, a1.w};
            float br[8] = {b0.x, b0.y, b0.z, b0.w, b1.x, b1.y, b1.z, b1.w};
#pragma unroll
            for (int i = 0; i < 8; i++)
#pragma unroll
                for (int j = 0; j < 8; j++) acc[i][j] += ar[i] * br[j];
        }
        __syncthreads();
    }

#pragma unroll
    for (int i = 0; i < 8; i++) {
        int c = c0 + ty * 8 + i;
        float mn = d_meanC[c], rs = d_rstdC[c];
        float ga = gamma[c], be = beta[c], bz = wz_b[c];
        float a = rs * ga;
        const float* xr = x + ((size_t)b * Cc + c) * HW + n0 + tx * 8;
        float* orow = out + ((size_t)b * Cc + c) * HW + n0 + tx * 8;
        float4 x0 = *(const float4*)xr;
        float4 x1 = *(const float4*)(xr + 4);
        float4 o0, o1;
        o0.x = (acc[i][0] + bz - mn) * a + be + x0.x;
        o0.y = (acc[i][1] + bz - mn) * a + be + x0.y;
        o0.z = (acc[i][2] + bz - mn) * a + be + x0.z;
        o0.w = (acc[i][3] + bz - mn) * a + be + x0.w;
        o1.x = (acc[i][4] + bz - mn) * a + be + x1.x;
        o1.y = (acc[i][5] + bz - mn) * a + be + x1.y;
        o1.z = (acc[i][6] + bz - mn) * a + be + x1.z;
        o1.w = (acc[i][7] + bz - mn) * a + be + x1.w;
        *(float4*)orow = o0;
        *(float4*)(orow + 4) = o1;
    }
}

// ---------------- launch ----------------------------------------------------
extern "C" void kernel_launch(void* const* d_in, const int* in_sizes, int n_in,
                              void* d_out, int out_size) {
    const float* x = (const float*)d_in[0];
    const float* g_w = (const float*)d_in[1];
    const float* g_b = (const float*)d_in[2];
    const float* th_w = (const float*)d_in[3];
    const float* th_b = (const float*)d_in[4];
    const float* ph_w = (const float*)d_in[5];
    const float* ph_b = (const float*)d_in[6];
    const float* wz_w = (const float*)d_in[7];
    const float* wz_b = (const float*)d_in[8];
    const float* gamma = (const float*)d_in[9];
    const float* beta = (const float*)d_in[10];
    float* out = (float*)d_out;

    const int att_smem = ATT_SMEM_FLOATS * 4;
    (void)cudaFuncSetAttribute(attn_kernel,
                               cudaFuncAttributeMaxDynamicSharedMemorySize, att_smem);

    zero_kernel<<<64, 256>>>();
    gemm1_kernel<<<dim3(HW / 128, 2, Bn), 256>>>(x, g_w, g_b, th_w, th_b, ph_w, ph_b);
    pool_kernel<<<(Bn * 192 * Mm + 255) / 256, 256>>>();
    attn_kernel<<<dim3(HW / 128, Bn), 256, att_smem>>>();
    mu_kernel<<<dim3(Gg, Bn), 256>>>();
    stats_kernel<<<128, 256>>>();
    meanvar_kernel<<<Cc, Gg>>>(wz_w, wz_b);
    gemm2_kernel<<<dim3(HW / 128, Cc / 128, Bn), 256>>>(x, wz_w, wz_b, gamma, beta, out);
}

// round 4
// speedup vs baseline: 1.2114x; 1.0641x over previous
#include <cuda_runtime.h>
#include <math.h>

#define Bn 8
#define Cc 512
#define HW 4096
#define Mm 1024
#define Dd 64
#define Gg 128

typedef unsigned long long ull;

// ---------------- packed f32x2 primitives (Blackwell) ----------------------
__device__ __forceinline__ ull pk2(float lo, float hi) {
    ull r;
    asm("mov.b64 %0, {%1, %2};" : "=l"(r) : "f"(lo), "f"(hi));
    return r;
}
__device__ __forceinline__ ull bc2(float v) { return pk2(v, v); }
__device__ __forceinline__ ull fma2(ull a, ull b, ull c) {
    ull d;
    asm("fma.rn.f32x2 %0, %1, %2, %3;" : "=l"(d) : "l"(a), "l"(b), "l"(c));
    return d;
}
__device__ __forceinline__ ull mul2(ull a, ull b) {
    ull d;
    asm("mul.rn.f32x2 %0, %1, %2;" : "=l"(d) : "l"(a), "l"(b));
    return d;
}
__device__ __forceinline__ void upk2(float& lo, float& hi, ull v) {
    asm("mov.b64 {%0, %1}, %2;" : "=f"(lo), "=f"(hi) : "l"(v));
}

// ---------------- scratch (device globals; no allocation allowed) ----------
__device__ float d_tpg[Bn * 256 * HW];
__device__ float d_phiP[Bn * Dd * Mm];
__device__ float d_gPT[Bn * Mm * Gg];    // pooled g, transposed [b][m][g]
__device__ float d_yT[Bn * Gg * HW];
__device__ float d_S[Gg * Gg];
__device__ float d_mu[Gg];
__device__ float d_meanC[Cc];
__device__ float d_rstdC[Cc];

// ---------------- fast exp on the FMA pipe (no MUFU) -----------------------
__device__ __forceinline__ float fast_exp(float x) {
    x = fmaxf(x, -87.0f);
    float t = fmaf(x, 1.4426950408889634f, 12582912.0f);
    float n = t - 12582912.0f;
    int e = __float_as_int(t) - 0x4B400000;
    float r = fmaf(n, -6.93145752e-1f, x);
    r = fmaf(n, -1.42860677e-6f, r);
    float p = 1.3888889e-3f;
    p = fmaf(p, r, 8.3333333e-3f);
    p = fmaf(p, r, 4.1666668e-2f);
    p = fmaf(p, r, 1.6666667e-1f);
    p = fmaf(p, r, 5.0e-1f);
    p = fmaf(p, r, 1.0f);
    p = fmaf(p, r, 1.0f);
    return __int_as_float(__float_as_int(p) + (e << 23));
}

// ---------------- kernel 0: zero S, mu -------------------------------------
__global__ void zero_kernel() {
    int i = blockIdx.x * 256 + threadIdx.x;
    if (i < Gg * Gg) d_S[i] = 0.0f;
    if (i < Gg) d_mu[i] = 0.0f;
}

// ---------------- kernel 1: fused conv1x1 (theta|phi|g), FFMA2 -------------
__global__ __launch_bounds__(256, 2) void gemm1_kernel(
    const float* __restrict__ x,
    const float* __restrict__ g_w, const float* __restrict__ g_b,
    const float* __restrict__ th_w, const float* __restrict__ th_b,
    const float* __restrict__ ph_w, const float* __restrict__ ph_b)
{
    __shared__ float As[16][128];
    __shared__ float Bs[16][128];
    __shared__ float bias_s[128];

    const int b = blockIdx.z;
    const int row0 = blockIdx.y * 128;
    const int n0 = blockIdx.x * 128;
    const int tid = threadIdx.x;
    const int tx = tid & 15, ty = tid >> 4;
    const float* xb = x + (size_t)b * Cc * HW;

    if (tid < 128) {
        int o = row0 + tid;
        float bv;
        if (o < 64) bv = th_b[o];
        else if (o < 128) bv = ph_b[o - 64];
        else bv = g_b[o - 128];
        bias_s[tid] = bv;
    }

    ull accp[8][4];   // [i][j-pair]
#pragma unroll
    for (int i = 0; i < 8; i++)
#pragma unroll
        for (int j = 0; j < 4; j++) accp[i][j] = 0ULL;

    const int am = tid >> 1;
    const int akq = (tid & 1) * 8;
    const float* wrow;
    {
        int o = row0 + am;
        if (o < 64) wrow = th_w + (size_t)o * Cc;
        else if (o < 128) wrow = ph_w + (size_t)(o - 64) * Cc;
        else wrow = g_w + (size_t)(o - 128) * Cc;
    }
    const int bkk = tid >> 4;
    const int bnq = (tid & 15) * 8;

    for (int k0 = 0; k0 < Cc; k0 += 16) {
        float4 wa = *(const float4*)(wrow + k0 + akq);
        float4 wb = *(const float4*)(wrow + k0 + akq + 4);
        As[akq + 0][am] = wa.x; As[akq + 1][am] = wa.y;
        As[akq + 2][am] = wa.z; As[akq + 3][am] = wa.w;
        As[akq + 4][am] = wb.x; As[akq + 5][am] = wb.y;
        As[akq + 6][am] = wb.z; As[akq + 7][am] = wb.w;

        const float* src = xb + (size_t)(k0 + bkk) * HW + n0 + bnq;
        float4 v0 = *(const float4*)src;
        float4 v1 = *(const float4*)(src + 4);
        *(float4*)&Bs[bkk][bnq] = v0;
        *(float4*)&Bs[bkk][bnq + 4] = v1;
        __syncthreads();

#pragma unroll
        for (int kk = 0; kk < 16; kk++) {
            float4 a0 = *(float4*)&As[kk][ty * 8];
            float4 a1 = *(float4*)&As[kk][ty * 8 + 4];
            ulonglong2 q0 = *(ulonglong2*)&Bs[kk][tx * 8];
            ulonglong2 q1 = *(ulonglong2*)&Bs[kk][tx * 8 + 4];
            ull bp[4] = {q0.x, q0.y, q1.x, q1.y};
            float ar[8] = {a0.x, a0.y, a0.z, a0.w, a1.x, a1.y, a1.z, a1.w};
#pragma unroll
            for (int i = 0; i < 8; i++) {
                ull ap = bc2(ar[i]);
#pragma unroll
                for (int j = 0; j < 4; j++) accp[i][j] = fma2(ap, bp[j], accp[i][j]);
            }
        }
        __syncthreads();
    }

    float* outp = d_tpg + ((size_t)b * 256 + row0) * HW + n0;
#pragma unroll
    for (int i = 0; i < 8; i++) {
        int r = ty * 8 + i;
        float bv = bias_s[r];
        float a[8];
        upk2(a[0], a[1], accp[i][0]); upk2(a[2], a[3], accp[i][1]);
        upk2(a[4], a[5], accp[i][2]); upk2(a[6], a[7], accp[i][3]);
        float4 o0, o1;
        o0.x = a[0] + bv; o0.y = a[1] + bv; o0.z = a[2] + bv; o0.w = a[3] + bv;
        o1.x = a[4] + bv; o1.y = a[5] + bv; o1.z = a[6] + bv; o1.w = a[7] + bv;
        *(float4*)(outp + (size_t)r * HW + tx * 8) = o0;
        *(float4*)(outp + (size_t)r * HW + tx * 8 + 4) = o1;
    }
}

// ---------------- kernel 2: 2x2 maxpool of phi/g rows ----------------------
__global__ void pool_kernel() {
    int idx = blockIdx.x * 256 + threadIdx.x;
    if (idx >= Bn * 192 * Mm) return;
    int pm = idx & (Mm - 1);
    int c = (idx >> 10) % 192;
    int b = idx / (192 * Mm);
    int ph = pm >> 5, pw = pm & 31;
    const float* src = d_tpg + ((size_t)b * 256 + 64 + c) * HW + (size_t)(ph * 2) * 64 + pw * 2;
    float v = fmaxf(fmaxf(src[0], src[1]), fmaxf(src[64], src[65]));
    if (c < 64) d_phiP[((size_t)b * Dd + c) * Mm + pm] = v;
    else d_gPT[((size_t)b * Mm + pm) * Gg + (c - 64)] = v;
}

// ---------------- kernel 3: fused attention (flash-style), FFMA2 -----------
#define ATT_SMEM_FLOATS (8192 + 4096 + 8448 + 8448 + 256)
__global__ __launch_bounds__(256, 1) void attn_kernel() {
    extern __shared__ float sm[];
    float* th_s = sm;                    // [c][n] stride 128
    float* phi_s = sm + 8192;            // [c][m] stride 64
    float* P_s = sm + 12288;             // [m][n] stride 132
    float* G_s = sm + 20736;             // [m][g] stride 132
    float* scale_s = sm + 29184;         // [128]
    float* l_s = sm + 29312;             // [128]

    const int b = blockIdx.y;
    const int n0 = blockIdx.x * 128;
    const int tid = threadIdx.x;
    const int tx = tid & 15, ty = tid >> 4;
    const int ty8 = ty * 8, tx4 = tx * 4, tx8 = tx * 8;

    const float* thg = d_tpg + (size_t)b * 256 * HW + n0;
    for (int f = tid; f < 64 * 32; f += 256) {
        int c = f >> 5, nq = (f & 31) * 4;
        *(float4*)&th_s[c * 128 + nq] = *(const float4*)(thg + (size_t)c * HW + nq);
    }

    float rm[8], l[8];
    ull accp[4][8];   // [n-pair][g]
#pragma unroll
    for (int i = 0; i < 8; i++) { rm[i] = -1e30f; l[i] = 0.0f; }
#pragma unroll
    for (int r = 0; r < 4; r++)
#pragma unroll
        for (int u = 0; u < 8; u++) accp[r][u] = 0ULL;

    const float* phig = d_phiP + (size_t)b * Dd * Mm;
    const float* gTg = d_gPT + (size_t)b * Mm * Gg;

    for (int m0 = 0; m0 < Mm; m0 += 64) {
        __syncthreads();
        for (int f = tid; f < 64 * 16; f += 256) {
            int c = f >> 4, mq = (f & 15) * 4;
            *(float4*)&phi_s[c * 64 + mq] = *(const float4*)(phig + (size_t)c * Mm + m0 + mq);
        }
        for (int f = tid; f < 64 * 32; f += 256) {
            int m = f >> 5, gq = (f & 31) * 4;
            *(float4*)&G_s[m * 132 + gq] = *(const float4*)(gTg + (size_t)(m0 + m) * Gg + gq);
        }
        __syncthreads();

        // scores: packed along n (ty8 pairs), 4 m per thread
        ull sp[4][4];
#pragma unroll
        for (int i = 0; i < 4; i++)
#pragma unroll
            for (int j = 0; j < 4; j++) sp[i][j] = 0ULL;
#pragma unroll 8
        for (int c = 0; c < 64; c++) {
            ulonglong2 t0 = *(ulonglong2*)&th_s[c * 128 + ty8];
            ulonglong2 t1 = *(ulonglong2*)&th_s[c * 128 + ty8 + 4];
            ull ap[4] = {t0.x, t0.y, t1.x, t1.y};
            float4 bb = *(float4*)&phi_s[c * 64 + tx4];
            ull bp[4] = {bc2(bb.x), bc2(bb.y), bc2(bb.z), bc2(bb.w)};
#pragma unroll
            for (int i = 0; i < 4; i++)
#pragma unroll
                for (int j = 0; j < 4; j++) sp[i][j] = fma2(ap[i], bp[j], sp[i][j]);
        }
        // unpack to scalars for softmax
        float s[8][4];
#pragma unroll
        for (int i = 0; i < 4; i++)
#pragma unroll
            for (int j = 0; j < 4; j++) upk2(s[2 * i][j], s[2 * i + 1][j], sp[i][j]);

        float sc[8];
#pragma unroll
        for (int i = 0; i < 8; i++) {
            float mx = fmaxf(fmaxf(s[i][0], s[i][1]), fmaxf(s[i][2], s[i][3]));
#pragma unroll
            for (int off = 8; off >= 1; off >>= 1)
                mx = fmaxf(mx, __shfl_xor_sync(0xffffffffu, mx, off));
            float nm = fmaxf(rm[i], mx);
            sc[i] = fast_exp(rm[i] - nm);
            rm[i] = nm;
            float ps = 0.0f;
#pragma unroll
            for (int j = 0; j < 4; j++) {
                s[i][j] = fast_exp(s[i][j] - nm);
                ps += s[i][j];
            }
#pragma unroll
            for (int off = 8; off >= 1; off >>= 1)
                ps += __shfl_xor_sync(0xffffffffu, ps, off);
            l[i] = l[i] * sc[i] + ps;
        }
        if (tx == 0) {
#pragma unroll
            for (int i = 0; i < 8; i++) scale_s[ty8 + i] = sc[i];
        }
#pragma unroll
        for (int j = 0; j < 4; j++) {
            float4 lo, hi;
            lo.x = s[0][j]; lo.y = s[1][j]; lo.z = s[2][j]; lo.w = s[3][j];
            hi.x = s[4][j]; hi.y = s[5][j]; hi.z = s[6][j]; hi.w = s[7][j];
            *(float4*)&P_s[(tx4 + j) * 132 + ty8] = lo;
            *(float4*)&P_s[(tx4 + j) * 132 + ty8 + 4] = hi;
        }
        __syncthreads();

        // rescale acc (PV rows n = tx8+r), packed pairs
        {
            ulonglong2 s0 = *(ulonglong2*)&scale_s[tx8];
            ulonglong2 s1 = *(ulonglong2*)&scale_s[tx8 + 4];
            ull srp[4] = {s0.x, s0.y, s1.x, s1.y};
#pragma unroll
            for (int r = 0; r < 4; r++)
#pragma unroll
                for (int u = 0; u < 8; u++) accp[r][u] = mul2(accp[r][u], srp[r]);
        }
        // y += P * G   (P pairs straight from LDS.128)
#pragma unroll 4
        for (int m = 0; m < 64; m++) {
            ulonglong2 p0 = *(ulonglong2*)&P_s[m * 132 + tx8];
            ulonglong2 p1 = *(ulonglong2*)&P_s[m * 132 + tx8 + 4];
            ull pp[4] = {p0.x, p0.y, p1.x, p1.y};
            float4 g0 = *(float4*)&G_s[m * 132 + ty8];
            float4 g1 = *(float4*)&G_s[m * 132 + ty8 + 4];
            float gu[8] = {g0.x, g0.y, g0.z, g0.w, g1.x, g1.y, g1.z, g1.w};
#pragma unroll
            for (int u = 0; u < 8; u++) {
                ull gp = bc2(gu[u]);
#pragma unroll
                for (int r = 0; r < 4; r++) accp[r][u] = fma2(pp[r], gp, accp[r][u]);
            }
        }
    }

    __syncthreads();
    if (tx == 0) {
#pragma unroll
        for (int i = 0; i < 8; i++) l_s[ty8 + i] = l[i];
    }
    __syncthreads();

    float inv[8];
    {
        float4 l0 = *(float4*)&l_s[tx8];
        float4 l1 = *(float4*)&l_s[tx8 + 4];
        inv[0] = 1.0f / l0.x; inv[1] = 1.0f / l0.y;
        inv[2] = 1.0f / l0.z; inv[3] = 1.0f / l0.w;
        inv[4] = 1.0f / l1.x; inv[5] = 1.0f / l1.y;
        inv[6] = 1.0f / l1.z; inv[7] = 1.0f / l1.w;
    }
    __syncthreads();

    float* yst = sm;   // reuse: [g][n] stride 132
#pragma unroll
    for (int u = 0; u < 8; u++) {
        float a[8];
        upk2(a[0], a[1], accp[0][u]); upk2(a[2], a[3], accp[1][u]);
        upk2(a[4], a[5], accp[2][u]); upk2(a[6], a[7], accp[3][u]);
        float4 lo, hi;
        lo.x = a[0] * inv[0]; lo.y = a[1] * inv[1];
        lo.z = a[2] * inv[2]; lo.w = a[3] * inv[3];
        hi.x = a[4] * inv[4]; hi.y = a[5] * inv[5];
        hi.z = a[6] * inv[6]; hi.w = a[7] * inv[7];
        *(float4*)&yst[(ty8 + u) * 132 + tx8] = lo;
        *(float4*)&yst[(ty8 + u) * 132 + tx8 + 4] = hi;
    }
    __syncthreads();

    float* yout = d_yT + (size_t)b * Gg * HW + n0;
    for (int f = tid; f < 128 * 32; f += 256) {
        int g = f >> 5, nq = (f & 31) * 4;
        *(float4*)(yout + (size_t)g * HW + nq) = *(float4*)&yst[g * 132 + nq];
    }
}

// ---------------- kernel 4: mu[g] = sum_{b,n} y (atomic partials) ----------
__global__ void mu_kernel() {
    int g = blockIdx.x;
    int b = blockIdx.y;
    int tid = threadIdx.x;
    float s = 0.0f;
    const float* p = d_yT + ((size_t)b * Gg + g) * HW;
    for (int n = tid; n < HW; n += 256) s += p[n];
    __shared__ float red[256];
    red[tid] = s;
    __syncthreads();
    for (int off = 128; off >= 1; off >>= 1) {
        if (tid < off) red[tid] += red[tid + off];
        __syncthreads();
    }
    if (tid == 0) atomicAdd(&d_mu[g], red[0]);
}

// ---------------- kernel 5: S = sum Y Y^T (syrk, FFMA2) --------------------
__global__ __launch_bounds__(256, 2) void stats_kernel() {
    __shared__ float ys[32 * 132];
    const int b = blockIdx.x >> 4;
    const int nbase = (blockIdx.x & 15) * 256;
    const int tid = threadIdx.x;
    const int tx = tid & 15, ty = tid >> 4;

    ull Sap[8][4];
#pragma unroll
    for (int i = 0; i < 8; i++)
#pragma unroll
        for (int j = 0; j < 4; j++) Sap[i][j] = 0ULL;

    const float* yb = d_yT + (size_t)b * Gg * HW + nbase;
    for (int nc = 0; nc < 256; nc += 32) {
        for (int i = tid; i < 1024; i += 256) {
            int g = i >> 3, nq = (i & 7) * 4;
            float4 v = *(const float4*)(yb + (size_t)g * HW + nc + nq);
            ys[(nq + 0) * 132 + g] = v.x;
            ys[(nq + 1) * 132 + g] = v.y;
            ys[(nq + 2) * 132 + g] = v.z;
            ys[(nq + 3) * 132 + g] = v.w;
        }
        __syncthreads();
#pragma unroll 4
        for (int nn = 0; nn < 32; nn++) {
            float4 u0 = *(float4*)&ys[nn * 132 + ty * 8];
            float4 u1 = *(float4*)&ys[nn * 132 + ty * 8 + 4];
            ulonglong2 v0 = *(ulonglong2*)&ys[nn * 132 + tx * 8];
            ulonglong2 v1 = *(ulonglong2*)&ys[nn * 132 + tx * 8 + 4];
            ull vp[4] = {v0.x, v0.y, v1.x, v1.y};
            float ur[8] = {u0.x, u0.y, u0.z, u0.w, u1.x, u1.y, u1.z, u1.w};
#pragma unroll
            for (int i = 0; i < 8; i++) {
                ull up = bc2(ur[i]);
#pragma unroll
                for (int j = 0; j < 4; j++) Sap[i][j] = fma2(up, vp[j], Sap[i][j]);
            }
        }
        __syncthreads();
    }
#pragma unroll
    for (int i = 0; i < 8; i++)
#pragma unroll
        for (int j = 0; j < 4; j++) {
            float lo, hi;
            upk2(lo, hi, Sap[i][j]);
            atomicAdd(&d_S[(ty * 8 + i) * Gg + tx * 8 + 2 * j], lo);
            atomicAdd(&d_S[(ty * 8 + i) * Gg + tx * 8 + 2 * j + 1], hi);
        }
}

// ---------------- kernel 6: per-channel BN mean/rstd (analytic) ------------
__global__ void meanvar_kernel(const float* __restrict__ wz_w,
                               const float* __restrict__ wz_b) {
    const int c = blockIdx.x;
    const int g = threadIdx.x;
    __shared__ float wsh[Gg];
    __shared__ double red[Gg];
    wsh[g] = wz_w[(size_t)c * Gg + g];
    __syncthreads();
    double t = 0.0;
    for (int gp = 0; gp < Gg; gp++)
        t += (double)d_S[g * Gg + gp] * (double)wsh[gp];
    red[g] = t * (double)wsh[g];
    __syncthreads();
    for (int off = 64; off >= 1; off >>= 1) {
        if (g < off) red[g] += red[g + off];
        __syncthreads();
    }
    double wtsw = red[0];
    __syncthreads();
    red[g] = (double)wsh[g] * (double)d_mu[g];
    __syncthreads();
    for (int off = 64; off >= 1; off >>= 1) {
        if (g < off) red[g] += red[g + off];
        __syncthreads();
    }
    if (g == 0) {
        double wm = red[0];
        double inv = 1.0 / (double)(Bn * HW);
        double bz = (double)wz_b[c];
        double mean = wm * inv + bz;
        double e2 = wtsw * inv + 2.0 * bz * wm * inv + bz * bz;
        double var = e2 - mean * mean;
        d_meanC[c] = (float)mean;
        d_rstdC[c] = (float)rsqrt(var + 1e-5);
    }
}

// ---------------- kernel 7: wz GEMM + BN + residual, FFMA2 -----------------
__global__ __launch_bounds__(256, 2) void gemm2_kernel(
    const float* __restrict__ x,
    const float* __restrict__ wz_w, const float* __restrict__ wz_b,
    const float* __restrict__ gamma, const float* __restrict__ beta,
    float* __restrict__ out)
{
    __shared__ float As[16][128];
    __shared__ float Bs[16][128];
    const int b = blockIdx.z;
    const int c0 = blockIdx.y * 128;
    const int n0 = blockIdx.x * 128;
    const int tid = threadIdx.x;
    const int tx = tid & 15, ty = tid >> 4;

    ull accp[8][4];
#pragma unroll
    for (int i = 0; i < 8; i++)
#pragma unroll
        for (int j = 0; j < 4; j++) accp[i][j] = 0ULL;

    const int am = tid >> 1;
    const int akq = (tid & 1) * 8;
    const float* wrow = wz_w + (size_t)(c0 + am) * Gg;
    const int bkk = tid >> 4;
    const int bnq = (tid & 15) * 8;
    const float* yb = d_yT + (size_t)b * Gg * HW;

    for (int k0 = 0; k0 < Gg; k0 += 16) {
        float4 wa = *(const float4*)(wrow + k0 + akq);
        float4 wb = *(const float4*)(wrow + k0 + akq + 4);
        As[akq + 0][am] = wa.x; As[akq + 1][am] = wa.y;
        As[akq + 2][am] = wa.z; As[akq + 3][am] = wa.w;
        As[akq + 4][am] = wb.x; As[akq + 5][am] = wb.y;
        As[akq + 6][am] = wb.z; As[akq + 7][am] = wb.w;

        const float* src = yb + (size_t)(k0 + bkk) * HW + n0 + bnq;
        float4 v0 = *(const float4*)src;
        float4 v1 = *(const float4*)(src + 4);
        *(float4*)&Bs[bkk][bnq] = v0;
        *(float4*)&Bs[bkk][bnq + 4] = v1;
        __syncthreads();

#pragma unroll
        for (int kk = 0; kk < 16; kk++) {
            float4 a0 = *(float4*)&As[kk][ty * 8];
            float4 a1 = *(float4*)&As[kk][ty * 8 + 4];
            ulonglong2 q0 = *(ulonglong2*)&Bs[kk][tx * 8];
            ulonglong2 q1 = *(ulonglong2*)&Bs[kk][tx * 8 + 4];
            ull bp[4] = {q0.x, q0.y, q1.x, q1.y};
            float ar[8] = {a0.x, a0.y, a0.z, a0.w, a1.x, a1.y, a1.z, a1.w};
#pragma unroll
            for (int i = 0; i < 8; i++) {
                ull ap = bc2(ar[i]);
#pragma unroll
                for (int j = 0; j < 4; j++) accp[i][j] = fma2(ap, bp[j], accp[i][j]);
            }
        }
        __syncthreads();
    }

#pragma unroll
    for (int i = 0; i < 8; i++) {
        int c = c0 + ty * 8 + i;
        float mn = d_meanC[c], rs = d_rstdC[c];
        float ga = gamma[c], be = beta[c], bz = wz_b[c];
        float a = rs * ga;
        float av[8];
        upk2(av[0], av[1], accp[i][0]); upk2(av[2], av[3], accp[i][1]);
        upk2(av[4], av[5], accp[i][2]); upk2(av[6], av[7], accp[i][3]);
        const float* xr = x + ((size_t)b * Cc + c) * HW + n0 + tx * 8;
        float* orow = out + ((size_t)b * Cc + c) * HW + n0 + tx * 8;
        float4 x0 = *(const float4*)xr;
        float4 x1 = *(const float4*)(xr + 4);
        float4 o0, o1;
        o0.x = (av[0] + bz - mn) * a + be + x0.x;
        o0.y = (av[1] + bz - mn) * a + be + x0.y;
        o0.z = (av[2] + bz - mn) * a + be + x0.z;
        o0.w = (av[3] + bz - mn) * a + be + x0.w;
        o1.x = (av[4] + bz - mn) * a + be + x1.x;
        o1.y = (av[5] + bz - mn) * a + be + x1.y;
        o1.z = (av[6] + bz - mn) * a + be + x1.z;
        o1.w = (av[7] + bz - mn) * a + be + x1.w;
        *(float4*)orow = o0;
        *(float4*)(orow + 4) = o1;
    }
}

// ---------------- launch ----------------------------------------------------
extern "C" void kernel_launch(void* const* d_in, const int* in_sizes, int n_in,
                              void* d_out, int out_size) {
    const float* x = (const float*)d_in[0];
    const float* g_w = (const float*)d_in[1];
    const float* g_b = (const float*)d_in[2];
    const float* th_w = (const float*)d_in[3];
    const float* th_b = (const float*)d_in[4];
    const float* ph_w = (const float*)d_in[5];
    const float* ph_b = (const float*)d_in[6];
    const float* wz_w = (const float*)d_in[7];
    const float* wz_b = (const float*)d_in[8];
    const float* gamma = (const float*)d_in[9];
    const float* beta = (const float*)d_in[10];
    float* out = (float*)d_out;

    const int att_smem = ATT_SMEM_FLOATS * 4;
    (void)cudaFuncSetAttribute(attn_kernel,
                               cudaFuncAttributeMaxDynamicSharedMemorySize, att_smem);

    zero_kernel<<<64, 256>>>();
    gemm1_kernel<<<dim3(HW / 128, 2, Bn), 256>>>(x, g_w, g_b, th_w, th_b, ph_w, ph_b);
    pool_kernel<<<(Bn * 192 * Mm + 255) / 256, 256>>>();
    attn_kernel<<<dim3(HW / 128, Bn), 256, att_smem>>>();
    mu_kernel<<<dim3(Gg, Bn), 256>>>();
    stats_kernel<<<128, 256>>>();
    meanvar_kernel<<<Cc, Gg>>>(wz_w, wz_b);
    gemm2_kernel<<<dim3(HW / 128, Cc / 128, Bn), 256>>>(x, wz_w, wz_b, gamma, beta, out);
}

// round 5
// speedup vs baseline: 1.2635x; 1.0430x over previous
#include <cuda_runtime.h>
#include <math.h>

#define Bn 8
#define Cc 512
#define HW 4096
#define Mm 1024
#define Dd 64
#define Gg 128

typedef unsigned long long ull;

// ---------------- packed f32x2 primitives (Blackwell) ----------------------
__device__ __forceinline__ ull pk2(float lo, float hi) {
    ull r;
    asm("mov.b64 %0, {%1, %2};" : "=l"(r) : "f"(lo), "f"(hi));
    return r;
}
__device__ __forceinline__ ull bc2(float v) { return pk2(v, v); }
__device__ __forceinline__ ull fma2(ull a, ull b, ull c) {
    ull d;
    asm("fma.rn.f32x2 %0, %1, %2, %3;" : "=l"(d) : "l"(a), "l"(b), "l"(c));
    return d;
}
__device__ __forceinline__ ull mul2(ull a, ull b) {
    ull d;
    asm("mul.rn.f32x2 %0, %1, %2;" : "=l"(d) : "l"(a), "l"(b));
    return d;
}
__device__ __forceinline__ void upk2(float& lo, float& hi, ull v) {
    asm("mov.b64 {%0, %1}, %2;" : "=f"(lo), "=f"(hi) : "l"(v));
}

// ---------------- scratch ---------------------------------------------------
__device__ float d_tpg[Bn * 256 * HW];
__device__ float d_phiP[Bn * Dd * Mm];
__device__ float d_gPT[Bn * Mm * Gg];    // pooled g, transposed [b][m][g]
__device__ float d_yT[Bn * Gg * HW];
__device__ float d_S[Gg * Gg];
__device__ float d_mu[Gg];
__device__ float d_meanC[Cc];
__device__ float d_rstdC[Cc];

// ---------------- fast exp on the FMA pipe (no MUFU) -----------------------
__device__ __forceinline__ float fast_exp(float x) {
    x = fmaxf(x, -87.0f);
    float t = fmaf(x, 1.4426950408889634f, 12582912.0f);
    float n = t - 12582912.0f;
    int e = __float_as_int(t) - 0x4B400000;
    float r = fmaf(n, -6.93145752e-1f, x);
    r = fmaf(n, -1.42860677e-6f, r);
    float p = 1.3888889e-3f;
    p = fmaf(p, r, 8.3333333e-3f);
    p = fmaf(p, r, 4.1666668e-2f);
    p = fmaf(p, r, 1.6666667e-1f);
    p = fmaf(p, r, 5.0e-1f);
    p = fmaf(p, r, 1.0f);
    p = fmaf(p, r, 1.0f);
    return __int_as_float(__float_as_int(p) + (e << 23));
}

// ---------------- kernel 0: zero S, mu -------------------------------------
__global__ void zero_kernel() {
    int i = blockIdx.x * 256 + threadIdx.x;
    if (i < Gg * Gg) d_S[i] = 0.0f;
    if (i < Gg) d_mu[i] = 0.0f;
}

// ---------------- kernel 1: fused conv1x1 (theta|phi|g), FFMA2 -------------
__global__ __launch_bounds__(256, 2) void gemm1_kernel(
    const float* __restrict__ x,
    const float* __restrict__ g_w, const float* __restrict__ g_b,
    const float* __restrict__ th_w, const float* __restrict__ th_b,
    const float* __restrict__ ph_w, const float* __restrict__ ph_b)
{
    __shared__ float As[16][128];
    __shared__ float Bs[16][128];
    __shared__ float bias_s[128];

    const int b = blockIdx.z;
    const int row0 = blockIdx.y * 128;
    const int n0 = blockIdx.x * 128;
    const int tid = threadIdx.x;
    const int tx = tid & 15, ty = tid >> 4;
    const float* xb = x + (size_t)b * Cc * HW;

    if (tid < 128) {
        int o = row0 + tid;
        float bv;
        if (o < 64) bv = th_b[o];
        else if (o < 128) bv = ph_b[o - 64];
        else bv = g_b[o - 128];
        bias_s[tid] = bv;
    }

    ull accp[8][4];
#pragma unroll
    for (int i = 0; i < 8; i++)
#pragma unroll
        for (int j = 0; j < 4; j++) accp[i][j] = 0ULL;

    const int am = tid >> 1;
    const int akq = (tid & 1) * 8;
    const float* wrow;
    {
        int o = row0 + am;
        if (o < 64) wrow = th_w + (size_t)o * Cc;
        else if (o < 128) wrow = ph_w + (size_t)(o - 64) * Cc;
        else wrow = g_w + (size_t)(o - 128) * Cc;
    }
    const int bkk = tid >> 4;
    const int bnq = (tid & 15) * 8;

    // prefetch first slab
    float4 wa = *(const float4*)(wrow + akq);
    float4 wb = *(const float4*)(wrow + akq + 4);
    const float* src0 = xb + (size_t)bkk * HW + n0 + bnq;
    float4 v0 = *(const float4*)src0;
    float4 v1 = *(const float4*)(src0 + 4);

    for (int k0 = 0; k0 < Cc; k0 += 16) {
        As[akq + 0][am] = wa.x; As[akq + 1][am] = wa.y;
        As[akq + 2][am] = wa.z; As[akq + 3][am] = wa.w;
        As[akq + 4][am] = wb.x; As[akq + 5][am] = wb.y;
        As[akq + 6][am] = wb.z; As[akq + 7][am] = wb.w;
        *(float4*)&Bs[bkk][bnq] = v0;
        *(float4*)&Bs[bkk][bnq + 4] = v1;
        __syncthreads();

        if (k0 + 16 < Cc) {
            wa = *(const float4*)(wrow + k0 + 16 + akq);
            wb = *(const float4*)(wrow + k0 + 16 + akq + 4);
            const float* src = xb + (size_t)(k0 + 16 + bkk) * HW + n0 + bnq;
            v0 = *(const float4*)src;
            v1 = *(const float4*)(src + 4);
        }

#pragma unroll
        for (int kk = 0; kk < 16; kk++) {
            float4 a0 = *(float4*)&As[kk][ty * 8];
            float4 a1 = *(float4*)&As[kk][ty * 8 + 4];
            ulonglong2 q0 = *(ulonglong2*)&Bs[kk][tx * 8];
            ulonglong2 q1 = *(ulonglong2*)&Bs[kk][tx * 8 + 4];
            ull bp[4] = {q0.x, q0.y, q1.x, q1.y};
            float ar[8] = {a0.x, a0.y, a0.z, a0.w, a1.x, a1.y, a1.z, a1.w};
#pragma unroll
            for (int i = 0; i < 8; i++) {
                ull ap = bc2(ar[i]);
#pragma unroll
                for (int j = 0; j < 4; j++) accp[i][j] = fma2(ap, bp[j], accp[i][j]);
            }
        }
        __syncthreads();
    }

    float* outp = d_tpg + ((size_t)b * 256 + row0) * HW + n0;
#pragma unroll
    for (int i = 0; i < 8; i++) {
        int r = ty * 8 + i;
        float bv = bias_s[r];
        float a[8];
        upk2(a[0], a[1], accp[i][0]); upk2(a[2], a[3], accp[i][1]);
        upk2(a[4], a[5], accp[i][2]); upk2(a[6], a[7], accp[i][3]);
        float4 o0, o1;
        o0.x = a[0] + bv; o0.y = a[1] + bv; o0.z = a[2] + bv; o0.w = a[3] + bv;
        o1.x = a[4] + bv; o1.y = a[5] + bv; o1.z = a[6] + bv; o1.w = a[7] + bv;
        *(float4*)(outp + (size_t)r * HW + tx * 8) = o0;
        *(float4*)(outp + (size_t)r * HW + tx * 8 + 4) = o1;
    }
}

// ---------------- kernel 2: 2x2 maxpool of phi/g rows ----------------------
__global__ void pool_kernel() {
    int idx = blockIdx.x * 256 + threadIdx.x;
    if (idx >= Bn * 192 * Mm) return;
    int pm = idx & (Mm - 1);
    int c = (idx >> 10) % 192;
    int b = idx / (192 * Mm);
    int ph = pm >> 5, pw = pm & 31;
    const float* src = d_tpg + ((size_t)b * 256 + 64 + c) * HW + (size_t)(ph * 2) * 64 + pw * 2;
    float v = fmaxf(fmaxf(src[0], src[1]), fmaxf(src[64], src[65]));
    if (c < 64) d_phiP[((size_t)b * Dd + c) * Mm + pm] = v;
    else d_gPT[((size_t)b * Mm + pm) * Gg + (c - 64)] = v;
}

// ---------------- kernel 3: fused attention, FFMA2, 2 CTAs/SM --------------
// smem: th[64*128] | P/phi union [64*132] | G [64*128] | scale[128] | l[128]
#define ATT_SMEM_FLOATS (8192 + 8448 + 8192 + 128 + 128)
__global__ __launch_bounds__(256, 2) void attn_kernel() {
    extern __shared__ float sm[];
    float* th_s = sm;                    // [c][n] stride 128
    float* phi_s = sm + 8192;            // [c][m] stride 64 (aliases P)
    float* P_s = sm + 8192;              // [m][n] stride 132
    float* G_s = sm + 16640;             // [m][g] stride 128
    float* scale_s = sm + 24832;         // [128]
    float* l_s = sm + 24960;             // [128]

    const int b = blockIdx.y;
    const int n0 = blockIdx.x * 128;
    const int tid = threadIdx.x;
    const int tx = tid & 15, ty = tid >> 4;
    const int ty8 = ty * 8, tx4 = tx * 4, tx8 = tx * 8;

    const float* thg = d_tpg + (size_t)b * 256 * HW + n0;
    for (int f = tid; f < 64 * 32; f += 256) {
        int c = f >> 5, nq = (f & 31) * 4;
        *(float4*)&th_s[c * 128 + nq] = *(const float4*)(thg + (size_t)c * HW + nq);
    }
    if (tid < 128) l_s[tid] = 0.0f;

    float rm[8];
    ull accp[4][8];   // [n-pair][g]
#pragma unroll
    for (int i = 0; i < 8; i++) rm[i] = -1e30f;
#pragma unroll
    for (int r = 0; r < 4; r++)
#pragma unroll
        for (int u = 0; u < 8; u++) accp[r][u] = 0ULL;

    const float* phig = d_phiP + (size_t)b * Dd * Mm;
    const float* gTg = d_gPT + (size_t)b * Mm * Gg;

    for (int m0 = 0; m0 < Mm; m0 += 64) {
        __syncthreads();   // prev PV done (P/G free); also covers th_s/l_s init
        for (int f = tid; f < 64 * 16; f += 256) {
            int c = f >> 4, mq = (f & 15) * 4;
            *(float4*)&phi_s[c * 64 + mq] = *(const float4*)(phig + (size_t)c * Mm + m0 + mq);
        }
        for (int f = tid; f < 64 * 32; f += 256) {
            int m = f >> 5, gq = (f & 31) * 4;
            *(float4*)&G_s[m * 128 + gq] = *(const float4*)(gTg + (size_t)(m0 + m) * Gg + gq);
        }
        __syncthreads();

        // scores: packed along n (ty8 pairs), 4 m per thread
        ull sp[4][4];
#pragma unroll
        for (int i = 0; i < 4; i++)
#pragma unroll
            for (int j = 0; j < 4; j++) sp[i][j] = 0ULL;
#pragma unroll 8
        for (int c = 0; c < 64; c++) {
            ulonglong2 t0 = *(ulonglong2*)&th_s[c * 128 + ty8];
            ulonglong2 t1 = *(ulonglong2*)&th_s[c * 128 + ty8 + 4];
            ull ap[4] = {t0.x, t0.y, t1.x, t1.y};
            float4 bb = *(float4*)&phi_s[c * 64 + tx4];
            ull bp[4] = {bc2(bb.x), bc2(bb.y), bc2(bb.z), bc2(bb.w)};
#pragma unroll
            for (int i = 0; i < 4; i++)
#pragma unroll
                for (int j = 0; j < 4; j++) sp[i][j] = fma2(ap[i], bp[j], sp[i][j]);
        }
        float s[8][4];
#pragma unroll
        for (int i = 0; i < 4; i++)
#pragma unroll
            for (int j = 0; j < 4; j++) upk2(s[2 * i][j], s[2 * i + 1][j], sp[i][j]);

        float sc[8], psum[8];
#pragma unroll
        for (int i = 0; i < 8; i++) {
            float mx = fmaxf(fmaxf(s[i][0], s[i][1]), fmaxf(s[i][2], s[i][3]));
#pragma unroll
            for (int off = 8; off >= 1; off >>= 1)
                mx = fmaxf(mx, __shfl_xor_sync(0xffffffffu, mx, off));
            float nm = fmaxf(rm[i], mx);
            sc[i] = fast_exp(rm[i] - nm);
            rm[i] = nm;
            float ps = 0.0f;
#pragma unroll
            for (int j = 0; j < 4; j++) {
                s[i][j] = fast_exp(s[i][j] - nm);
                ps += s[i][j];
            }
#pragma unroll
            for (int off = 8; off >= 1; off >>= 1)
                ps += __shfl_xor_sync(0xffffffffu, ps, off);
            psum[i] = ps;
        }
        if (tx == 0) {
#pragma unroll
            for (int i = 0; i < 8; i++) {
                scale_s[ty8 + i] = sc[i];
                l_s[ty8 + i] = l_s[ty8 + i] * sc[i] + psum[i];
            }
        }
        __syncthreads();   // phi reads done; scale_s visible

        // rescale acc (PV rows n = tx8+r), packed pairs
        {
            ulonglong2 s0 = *(ulonglong2*)&scale_s[tx8];
            ulonglong2 s1 = *(ulonglong2*)&scale_s[tx8 + 4];
            ull srp[4] = {s0.x, s0.y, s1.x, s1.y};
#pragma unroll
            for (int r = 0; r < 4; r++)
#pragma unroll
                for (int u = 0; u < 8; u++) accp[r][u] = mul2(accp[r][u], srp[r]);
        }
        // write P [m][n] (clobbers phi — safe after barrier)
#pragma unroll
        for (int j = 0; j < 4; j++) {
            float4 lo, hi;
            lo.x = s[0][j]; lo.y = s[1][j]; lo.z = s[2][j]; lo.w = s[3][j];
            hi.x = s[4][j]; hi.y = s[5][j]; hi.z = s[6][j]; hi.w = s[7][j];
            *(float4*)&P_s[(tx4 + j) * 132 + ty8] = lo;
            *(float4*)&P_s[(tx4 + j) * 132 + ty8 + 4] = hi;
        }
        __syncthreads();   // P visible

        // y += P * G
#pragma unroll 4
        for (int m = 0; m < 64; m++) {
            ulonglong2 p0 = *(ulonglong2*)&P_s[m * 132 + tx8];
            ulonglong2 p1 = *(ulonglong2*)&P_s[m * 132 + tx8 + 4];
            ull pp[4] = {p0.x, p0.y, p1.x, p1.y};
            float4 g0 = *(float4*)&G_s[m * 128 + ty8];
            float4 g1 = *(float4*)&G_s[m * 128 + ty8 + 4];
            float gu[8] = {g0.x, g0.y, g0.z, g0.w, g1.x, g1.y, g1.z, g1.w};
#pragma unroll
            for (int u = 0; u < 8; u++) {
                ull gp = bc2(gu[u]);
#pragma unroll
                for (int r = 0; r < 4; r++) accp[r][u] = fma2(pp[r], gp, accp[r][u]);
            }
        }
    }

    __syncthreads();   // all PV reads done; l_s final
    float inv[8];
    {
        float4 l0 = *(float4*)&l_s[tx8];
        float4 l1 = *(float4*)&l_s[tx8 + 4];
        inv[0] = 1.0f / l0.x; inv[1] = 1.0f / l0.y;
        inv[2] = 1.0f / l0.z; inv[3] = 1.0f / l0.w;
        inv[4] = 1.0f / l1.x; inv[5] = 1.0f / l1.y;
        inv[6] = 1.0f / l1.z; inv[7] = 1.0f / l1.w;
    }
    __syncthreads();   // smem free for staging

    float* yst = sm;   // [g][n] stride 132 (16896 floats, fits)
#pragma unroll
    for (int u = 0; u < 8; u++) {
        float a[8];
        upk2(a[0], a[1], accp[0][u]); upk2(a[2], a[3], accp[1][u]);
        upk2(a[4], a[5], accp[2][u]); upk2(a[6], a[7], accp[3][u]);
        float y0 = a[0] * inv[0], y1 = a[1] * inv[1];
        float y2 = a[2] * inv[2], y3 = a[3] * inv[3];
        float y4 = a[4] * inv[4], y5 = a[5] * inv[5];
        float y6 = a[6] * inv[6], y7 = a[7] * inv[7];
        float4 lo, hi;
        lo.x = y0; lo.y = y1; lo.z = y2; lo.w = y3;
        hi.x = y4; hi.y = y5; hi.z = y6; hi.w = y7;
        *(float4*)&yst[(ty8 + u) * 132 + tx8] = lo;
        *(float4*)&yst[(ty8 + u) * 132 + tx8 + 4] = hi;
        // fold mu: sum over this thread's 8 n, reduce across tx, atomic per g
        float p = ((y0 + y1) + (y2 + y3)) + ((y4 + y5) + (y6 + y7));
#pragma unroll
        for (int off = 8; off >= 1; off >>= 1)
            p += __shfl_xor_sync(0xffffffffu, p, off);
        if (tx == 0) atomicAdd(&d_mu[ty8 + u], p);
    }
    __syncthreads();

    float* yout = d_yT + (size_t)b * Gg * HW + n0;
    for (int f = tid; f < 128 * 32; f += 256) {
        int g = f >> 5, nq = (f & 31) * 4;
        *(float4*)(yout + (size_t)g * HW + nq) = *(float4*)&yst[g * 132 + nq];
    }
}

// ---------------- kernel 5: S = sum Y Y^T (syrk, FFMA2) --------------------
__global__ __launch_bounds__(256, 2) void stats_kernel() {
    __shared__ float ys[32 * 132];
    const int b = blockIdx.x >> 4;
    const int nbase = (blockIdx.x & 15) * 256;
    const int tid = threadIdx.x;
    const int tx = tid & 15, ty = tid >> 4;

    ull Sap[8][4];
#pragma unroll
    for (int i = 0; i < 8; i++)
#pragma unroll
        for (int j = 0; j < 4; j++) Sap[i][j] = 0ULL;

    const float* yb = d_yT + (size_t)b * Gg * HW + nbase;
    for (int nc = 0; nc < 256; nc += 32) {
        for (int i = tid; i < 1024; i += 256) {
            int g = i >> 3, nq = (i & 7) * 4;
            float4 v = *(const float4*)(yb + (size_t)g * HW + nc + nq);
            ys[(nq + 0) * 132 + g] = v.x;
            ys[(nq + 1) * 132 + g] = v.y;
            ys[(nq + 2) * 132 + g] = v.z;
            ys[(nq + 3) * 132 + g] = v.w;
        }
        __syncthreads();
#pragma unroll 4
        for (int nn = 0; nn < 32; nn++) {
            float4 u0 = *(float4*)&ys[nn * 132 + ty * 8];
            float4 u1 = *(float4*)&ys[nn * 132 + ty * 8 + 4];
            ulonglong2 v0 = *(ulonglong2*)&ys[nn * 132 + tx * 8];
            ulonglong2 v1 = *(ulonglong2*)&ys[nn * 132 + tx * 8 + 4];
            ull vp[4] = {v0.x, v0.y, v1.x, v1.y};
            float ur[8] = {u0.x, u0.y, u0.z, u0.w, u1.x, u1.y, u1.z, u1.w};
#pragma unroll
            for (int i = 0; i < 8; i++) {
                ull up = bc2(ur[i]);
#pragma unroll
                for (int j = 0; j < 4; j++) Sap[i][j] = fma2(up, vp[j], Sap[i][j]);
            }
        }
        __syncthreads();
    }
#pragma unroll
    for (int i = 0; i < 8; i++)
#pragma unroll
        for (int j = 0; j < 4; j++) {
            float lo, hi;
            upk2(lo, hi, Sap[i][j]);
            atomicAdd(&d_S[(ty * 8 + i) * Gg + tx * 8 + 2 * j], lo);
            atomicAdd(&d_S[(ty * 8 + i) * Gg + tx * 8 + 2 * j + 1], hi);
        }
}

// ---------------- kernel 6: per-channel BN mean/rstd (analytic) ------------
__global__ void meanvar_kernel(const float* __restrict__ wz_w,
                               const float* __restrict__ wz_b) {
    const int c = blockIdx.x;
    const int g = threadIdx.x;
    __shared__ float wsh[Gg];
    __shared__ double red[Gg];
    wsh[g] = wz_w[(size_t)c * Gg + g];
    __syncthreads();
    double t = 0.0;
    for (int gp = 0; gp < Gg; gp++)
        t += (double)d_S[g * Gg + gp] * (double)wsh[gp];
    red[g] = t * (double)wsh[g];
    __syncthreads();
    for (int off = 64; off >= 1; off >>= 1) {
        if (g < off) red[g] += red[g + off];
        __syncthreads();
    }
    double wtsw = red[0];
    __syncthreads();
    red[g] = (double)wsh[g] * (double)d_mu[g];
    __syncthreads();
    for (int off = 64; off >= 1; off >>= 1) {
        if (g < off) red[g] += red[g + off];
        __syncthreads();
    }
    if (g == 0) {
        double wm = red[0];
        double inv = 1.0 / (double)(Bn * HW);
        double bz = (double)wz_b[c];
        double mean = wm * inv + bz;
        double e2 = wtsw * inv + 2.0 * bz * wm * inv + bz * bz;
        double var = e2 - mean * mean;
        d_meanC[c] = (float)mean;
        d_rstdC[c] = (float)rsqrt(var + 1e-5);
    }
}

// ---------------- kernel 7: wz GEMM + BN + residual, FFMA2 -----------------
__global__ __launch_bounds__(256, 2) void gemm2_kernel(
    const float* __restrict__ x,
    const float* __restrict__ wz_w, const float* __restrict__ wz_b,
    const float* __restrict__ gamma, const float* __restrict__ beta,
    float* __restrict__ out)
{
    __shared__ float As[16][128];
    __shared__ float Bs[16][128];
    const int b = blockIdx.z;
    const int c0 = blockIdx.y * 128;
    const int n0 = blockIdx.x * 128;
    const int tid = threadIdx.x;
    const int tx = tid & 15, ty = tid >> 4;

    ull accp[8][4];
#pragma unroll
    for (int i = 0; i < 8; i++)
#pragma unroll
        for (int j = 0; j < 4; j++) accp[i][j] = 0ULL;

    const int am = tid >> 1;
    const int akq = (tid & 1) * 8;
    const float* wrow = wz_w + (size_t)(c0 + am) * Gg;
    const int bkk = tid >> 4;
    const int bnq = (tid & 15) * 8;
    const float* yb = d_yT + (size_t)b * Gg * HW;

    float4 wa = *(const float4*)(wrow + akq);
    float4 wb = *(const float4*)(wrow + akq + 4);
    const float* src0 = yb + (size_t)bkk * HW + n0 + bnq;
    float4 v0 = *(const float4*)src0;
    float4 v1 = *(const float4*)(src0 + 4);

    for (int k0 = 0; k0 < Gg; k0 += 16) {
        As[akq + 0][am] = wa.x; As[akq + 1][am] = wa.y;
        As[akq + 2][am] = wa.z; As[akq + 3][am] = wa.w;
        As[akq + 4][am] = wb.x; As[akq + 5][am] = wb.y;
        As[akq + 6][am] = wb.z; As[akq + 7][am] = wb.w;
        *(float4*)&Bs[bkk][bnq] = v0;
        *(float4*)&Bs[bkk][bnq + 4] = v1;
        __syncthreads();

        if (k0 + 16 < Gg) {
            wa = *(const float4*)(wrow + k0 + 16 + akq);
            wb = *(const float4*)(wrow + k0 + 16 + akq + 4);
            const float* src = yb + (size_t)(k0 + 16 + bkk) * HW + n0 + bnq;
            v0 = *(const float4*)src;
            v1 = *(const float4*)(src + 4);
        }

#pragma unroll
        for (int kk = 0; kk < 16; kk++) {
            float4 a0 = *(float4*)&As[kk][ty * 8];
            float4 a1 = *(float4*)&As[kk][ty * 8 + 4];
            ulonglong2 q0 = *(ulonglong2*)&Bs[kk][tx * 8];
            ulonglong2 q1 = *(ulonglong2*)&Bs[kk][tx * 8 + 4];
            ull bp[4] = {q0.x, q0.y, q1.x, q1.y};
            float ar[8] = {a0.x, a0.y, a0.z, a0.w, a1.x, a1.y, a1.z, a1.w};
#pragma unroll
            for (int i = 0; i < 8; i++) {
                ull ap = bc2(ar[i]);
#pragma unroll
                for (int j = 0; j < 4; j++) accp[i][j] = fma2(ap, bp[j], accp[i][j]);
            }
        }
        __syncthreads();
    }

#pragma unroll
    for (int i = 0; i < 8; i++) {
        int c = c0 + ty * 8 + i;
        float mn = d_meanC[c], rs = d_rstdC[c];
        float ga = gamma[c], be = beta[c], bz = wz_b[c];
        float a = rs * ga;
        float av[8];
        upk2(av[0], av[1], accp[i][0]); upk2(av[2], av[3], accp[i][1]);
        upk2(av[4], av[5], accp[i][2]); upk2(av[6], av[7], accp[i][3]);
        const float* xr = x + ((size_t)b * Cc + c) * HW + n0 + tx * 8;
        float* orow = out + ((size_t)b * Cc + c) * HW + n0 + tx * 8;
        float4 x0 = *(const float4*)xr;
        float4 x1 = *(const float4*)(xr + 4);
        float4 o0, o1;
        o0.x = (av[0] + bz - mn) * a + be + x0.x;
        o0.y = (av[1] + bz - mn) * a + be + x0.y;
        o0.z = (av[2] + bz - mn) * a + be + x0.z;
        o0.w = (av[3] + bz - mn) * a + be + x0.w;
        o1.x = (av[4] + bz - mn) * a + be + x1.x;
        o1.y = (av[5] + bz - mn) * a + be + x1.y;
        o1.z = (av[6] + bz - mn) * a + be + x1.z;
        o1.w = (av[7] + bz - mn) * a + be + x1.w;
        *(float4*)orow = o0;
        *(float4*)(orow + 4) = o1;
    }
}

// ---------------- launch ----------------------------------------------------
extern "C" void kernel_launch(void* const* d_in, const int* in_sizes, int n_in,
                              void* d_out, int out_size) {
    const float* x = (const float*)d_in[0];
    const float* g_w = (const float*)d_in[1];
    const float* g_b = (const float*)d_in[2];
    const float* th_w = (const float*)d_in[3];
    const float* th_b = (const float*)d_in[4];
    const float* ph_w = (const float*)d_in[5];
    const float* ph_b = (const float*)d_in[6];
    const float* wz_w = (const float*)d_in[7];
    const float* wz_b = (const float*)d_in[8];
    const float* gamma = (const float*)d_in[9];
    const float* beta = (const float*)d_in[10];
    float* out = (float*)d_out;

    const int att_smem = ATT_SMEM_FLOATS * 4;
    (void)cudaFuncSetAttribute(attn_kernel,
                               cudaFuncAttributeMaxDynamicSharedMemorySize, att_smem);

    zero_kernel<<<64, 256>>>();
    gemm1_kernel<<<dim3(HW / 128, 2, Bn), 256>>>(x, g_w, g_b, th_w, th_b, ph_w, ph_b);
    pool_kernel<<<(Bn * 192 * Mm + 255) / 256, 256>>>();
    attn_kernel<<<dim3(HW / 128, Bn), 256, att_smem>>>();
    stats_kernel<<<128, 256>>>();
    meanvar_kernel<<<Cc, Gg>>>(wz_w, wz_b);
    gemm2_kernel<<<dim3(HW / 128, Cc / 128, Bn), 256>>>(x, wz_w, wz_b, gamma, beta, out);
}